// round 4
// baseline (speedup 1.0000x reference)
#include <cuda_runtime.h>
#include <math.h>

#define T_TOT 32768
#define DM    256
#define FFN   1024

// 128 MB scratch for fused[T, FFN] (allocation-free rule: __device__ global)
__device__ float g_fused[(size_t)T_TOT * FFN];

__device__ __forceinline__ float sigf(float z) {
    return 1.0f / (1.0f + __expf(-z));
}

// ---- f32x2 packed-math helpers (sm_103a FFMA2 path) -----------------------
__device__ __forceinline__ unsigned long long pack2(float lo, float hi) {
    unsigned long long r;
    asm("mov.b64 %0, {%1, %2};" : "=l"(r) : "f"(lo), "f"(hi));
    return r;
}
__device__ __forceinline__ void unpack2(unsigned long long v, float& lo, float& hi) {
    asm("mov.b64 {%0, %1}, %2;" : "=f"(lo), "=f"(hi) : "l"(v));
}
__device__ __forceinline__ unsigned long long fma2(unsigned long long a,
                                                   unsigned long long b,
                                                   unsigned long long c) {
    unsigned long long d;
    asm("fma.rn.f32x2 %0, %1, %2, %3;" : "=l"(d) : "l"(a), "l"(b), "l"(c));
    return d;
}
__device__ __forceinline__ unsigned long long add2(unsigned long long a,
                                                   unsigned long long b) {
    unsigned long long d;
    asm("add.rn.f32x2 %0, %1, %2;" : "=l"(d) : "l"(a), "l"(b));
    return d;
}

// ---------------------------------------------------------------------------
// Kernel 1: fused[t, j] = g * trop + (1-g) * classical
// Block tile 128 (tokens) x 64 (ffn), 256 threads, per-thread 8m x 4n.
// Double-buffered smem, K chunks of 16, LDG prefetch of chunk+1 overlapped
// with compute of chunk.
// ---------------------------------------------------------------------------
__global__ __launch_bounds__(256) void dtn_fused_kernel(
    const float* __restrict__ x,       // [T, 256]
    const float* __restrict__ Wt,      // [1024, 256]
    const float* __restrict__ bt,      // [1024]
    const float* __restrict__ sl_cvx,  // [1024, 8]
    const float* __restrict__ of_cvx,  // [1024, 8]
    const float* __restrict__ sl_ccv,  // [1024, 8]
    const float* __restrict__ of_ccv,  // [1024, 8]
    const float* __restrict__ alpha,   // [1024]
    const float* __restrict__ Wc,      // [256, 1024]
    const float* __restrict__ bc,      // [1024]
    const float* __restrict__ Wg,      // [256, 1024]
    const float* __restrict__ bg)      // [1024]
{
    __shared__ float xs [2][16][132];
    __shared__ float wts[2][16][68];
    __shared__ float wcs[2][16][68];
    __shared__ float wgs[2][16][68];

    const int tid = threadIdx.x;
    const int tx  = tid & 15;   // ffn dir, 4 cols each
    const int ty  = tid >> 4;   // token dir, 8 rows each
    const int m0  = blockIdx.y * 128;
    const int n0  = blockIdx.x * 64;

    // Load indexing (fixed per thread)
    const int xrow0 = tid >> 2;            // 0..63   (x rows, r=0)
    const int xrow1 = (tid + 256) >> 2;    // 64..127 (x rows, r=1)
    const int xkq   = tid & 3;             // k quad within chunk
    const int wrow  = tid >> 2;            // 0..63  (Wt row)
    const int krow  = tid >> 4;            // 0..15  (Wc/Wg k row)
    const int jq    = tid & 15;            // 0..15  (Wc/Wg n quad)

    const float NEG_INF = __int_as_float(0xff800000);
    float tmax[8][4];
    unsigned long long c2[8][2], g2[8][2];   // n-packed fp32 pairs
#pragma unroll
    for (int i = 0; i < 8; i++) {
        c2[i][0] = 0ull; c2[i][1] = 0ull; g2[i][0] = 0ull; g2[i][1] = 0ull;
#pragma unroll
        for (int j = 0; j < 4; j++) tmax[i][j] = NEG_INF;
    }

    float4 pxv0, pxv1, pwt, pwc, pwg;

    // ---- prefetch + store chunk 0 into buffer 0 ----
    {
        const int kc = 0;
        pxv0 = *(const float4*)(x  + (size_t)(m0 + xrow0) * DM + kc + xkq * 4);
        pxv1 = *(const float4*)(x  + (size_t)(m0 + xrow1) * DM + kc + xkq * 4);
        pwt  = *(const float4*)(Wt + (size_t)(n0 + wrow)  * DM + kc + xkq * 4);
        pwc  = *(const float4*)(Wc + (size_t)(kc + krow) * FFN + n0 + jq * 4);
        pwg  = *(const float4*)(Wg + (size_t)(kc + krow) * FFN + n0 + jq * 4);
        xs[0][xkq*4+0][xrow0] = pxv0.x; xs[0][xkq*4+1][xrow0] = pxv0.y;
        xs[0][xkq*4+2][xrow0] = pxv0.z; xs[0][xkq*4+3][xrow0] = pxv0.w;
        xs[0][xkq*4+0][xrow1] = pxv1.x; xs[0][xkq*4+1][xrow1] = pxv1.y;
        xs[0][xkq*4+2][xrow1] = pxv1.z; xs[0][xkq*4+3][xrow1] = pxv1.w;
        wts[0][xkq*4+0][wrow] = pwt.x;  wts[0][xkq*4+1][wrow] = pwt.y;
        wts[0][xkq*4+2][wrow] = pwt.z;  wts[0][xkq*4+3][wrow] = pwt.w;
        *(float4*)&wcs[0][krow][jq*4] = pwc;
        *(float4*)&wgs[0][krow][jq*4] = pwg;
    }
    __syncthreads();

    for (int ch = 0; ch < 16; ch++) {
        const int p = ch & 1;
        // ---- issue LDGs for chunk+1 (overlap with compute) ----
        if (ch < 15) {
            const int kc = (ch + 1) * 16;
            pxv0 = *(const float4*)(x  + (size_t)(m0 + xrow0) * DM + kc + xkq * 4);
            pxv1 = *(const float4*)(x  + (size_t)(m0 + xrow1) * DM + kc + xkq * 4);
            pwt  = *(const float4*)(Wt + (size_t)(n0 + wrow)  * DM + kc + xkq * 4);
            pwc  = *(const float4*)(Wc + (size_t)(kc + krow) * FFN + n0 + jq * 4);
            pwg  = *(const float4*)(Wg + (size_t)(kc + krow) * FFN + n0 + jq * 4);
        }

        // ---- compute on buffer p ----
#pragma unroll
        for (int kk = 0; kk < 16; kk++) {
            const float4 xa0 = *(const float4*)&xs[p][kk][ty * 8];
            const float4 xa1 = *(const float4*)&xs[p][kk][ty * 8 + 4];
            const float4 wa  = *(const float4*)&wts[p][kk][tx * 4];
            const float4 ca  = *(const float4*)&wcs[p][kk][tx * 4];
            const float4 ga  = *(const float4*)&wgs[p][kk][tx * 4];
            const float xm[8] = {xa0.x, xa0.y, xa0.z, xa0.w,
                                 xa1.x, xa1.y, xa1.z, xa1.w};
            const unsigned long long wp[2] = {pack2(wa.x, wa.y), pack2(wa.z, wa.w)};
            const unsigned long long cp[2] = {pack2(ca.x, ca.y), pack2(ca.z, ca.w)};
            const unsigned long long gp[2] = {pack2(ga.x, ga.y), pack2(ga.z, ga.w)};
#pragma unroll
            for (int mi = 0; mi < 8; mi++) {
                const unsigned long long xd = pack2(xm[mi], xm[mi]);
#pragma unroll
                for (int pp = 0; pp < 2; pp++) {
                    c2[mi][pp] = fma2(xd, cp[pp], c2[mi][pp]);
                    g2[mi][pp] = fma2(xd, gp[pp], g2[mi][pp]);
                    const unsigned long long t2 = add2(xd, wp[pp]);
                    float tlo, thi;
                    unpack2(t2, tlo, thi);
                    tmax[mi][2*pp+0] = fmaxf(tmax[mi][2*pp+0], tlo);
                    tmax[mi][2*pp+1] = fmaxf(tmax[mi][2*pp+1], thi);
                }
            }
        }

        // ---- store prefetched chunk into the other buffer ----
        if (ch < 15) {
            const int q = 1 - p;
            xs[q][xkq*4+0][xrow0] = pxv0.x; xs[q][xkq*4+1][xrow0] = pxv0.y;
            xs[q][xkq*4+2][xrow0] = pxv0.z; xs[q][xkq*4+3][xrow0] = pxv0.w;
            xs[q][xkq*4+0][xrow1] = pxv1.x; xs[q][xkq*4+1][xrow1] = pxv1.y;
            xs[q][xkq*4+2][xrow1] = pxv1.z; xs[q][xkq*4+3][xrow1] = pxv1.w;
            wts[q][xkq*4+0][wrow] = pwt.x;  wts[q][xkq*4+1][wrow] = pwt.y;
            wts[q][xkq*4+2][wrow] = pwt.z;  wts[q][xkq*4+3][wrow] = pwt.w;
            *(float4*)&wcs[q][krow][jq*4] = pwc;
            *(float4*)&wgs[q][krow][jq*4] = pwg;
        }
        __syncthreads();
    }

    // ---- Epilogue ----
#pragma unroll
    for (int ni = 0; ni < 4; ni++) {
        const int j = n0 + tx * 4 + ni;
        const float btj = bt[j];
        const float s   = sigf(alpha[j]);
        const float bcj = bc[j];
        const float bgj = bg[j];
        const float4 sc0 = *(const float4*)(sl_cvx + (size_t)j * 8);
        const float4 sc1 = *(const float4*)(sl_cvx + (size_t)j * 8 + 4);
        const float4 oc0 = *(const float4*)(of_cvx + (size_t)j * 8);
        const float4 oc1 = *(const float4*)(of_cvx + (size_t)j * 8 + 4);
        const float4 sv0 = *(const float4*)(sl_ccv + (size_t)j * 8);
        const float4 sv1 = *(const float4*)(sl_ccv + (size_t)j * 8 + 4);
        const float4 ov0 = *(const float4*)(of_ccv + (size_t)j * 8);
        const float4 ov1 = *(const float4*)(of_ccv + (size_t)j * 8 + 4);
#pragma unroll
        for (int mi = 0; mi < 8; mi++) {
            float clo, chi, glo, ghi;
            unpack2(c2[mi][ni >> 1], clo, chi);
            unpack2(g2[mi][ni >> 1], glo, ghi);
            const float accc = (ni & 1) ? chi : clo;
            const float accg = (ni & 1) ? ghi : glo;

            const float t = tmax[mi][ni] + btj;
            float cvx = fmaf(t, sc0.x, oc0.x);
            cvx = fmaxf(cvx, fmaf(t, sc0.y, oc0.y));
            cvx = fmaxf(cvx, fmaf(t, sc0.z, oc0.z));
            cvx = fmaxf(cvx, fmaf(t, sc0.w, oc0.w));
            cvx = fmaxf(cvx, fmaf(t, sc1.x, oc1.x));
            cvx = fmaxf(cvx, fmaf(t, sc1.y, oc1.y));
            cvx = fmaxf(cvx, fmaf(t, sc1.z, oc1.z));
            cvx = fmaxf(cvx, fmaf(t, sc1.w, oc1.w));
            float ccv = fmaf(t, sv0.x, ov0.x);
            ccv = fminf(ccv, fmaf(t, sv0.y, ov0.y));
            ccv = fminf(ccv, fmaf(t, sv0.z, ov0.z));
            ccv = fminf(ccv, fmaf(t, sv0.w, ov0.w));
            ccv = fminf(ccv, fmaf(t, sv1.x, ov1.x));
            ccv = fminf(ccv, fmaf(t, sv1.y, ov1.y));
            ccv = fminf(ccv, fmaf(t, sv1.z, ov1.z));
            ccv = fminf(ccv, fmaf(t, sv1.w, ov1.w));
            const float trop = s * cvx + (1.0f - s) * ccv;

            const float v   = accc + bcj;
            const float cls = 0.5f * v * (1.0f + erff(v * 0.70710678118654752f));
            const float g   = sigf(accg + bgj);

            g_fused[(size_t)(m0 + ty * 8 + mi) * FFN + j] =
                g * trop + (1.0f - g) * cls;
        }
    }
}

// ---------------------------------------------------------------------------
// Kernel 2: out[T, 256] = fused[T, 1024] @ Wd[1024, 256] + bd
// Block tile 128 x 128, 256 threads, per-thread 8m x 8n (two n-quads at
// tx*4 and 64+tx*4). m-packed f32x2 FMA. Double-buffered smem.
// ---------------------------------------------------------------------------
__global__ __launch_bounds__(256, 2) void dtn_out_kernel(
    const float* __restrict__ Wd,      // [1024, 256]
    const float* __restrict__ bd,      // [256]
    float* __restrict__ out)           // [T, 256]
{
    __shared__ float fs [2][16][132];
    __shared__ float wds[2][16][132];

    const int tid = threadIdx.x;
    const int tx  = tid & 15;   // n dir, quads at tx*4 and 64+tx*4
    const int ty  = tid >> 4;   // m dir, 8 each
    const int m0  = blockIdx.y * 128;
    const int n0  = blockIdx.x * 128;

    const int frow0 = tid >> 2;            // 0..63
    const int frow1 = (tid + 256) >> 2;    // 64..127
    const int fkq   = tid & 3;
    const int wk0   = tid >> 5;            // 0..7
    const int wk1   = (tid + 256) >> 5;    // 8..15
    const int wjq   = tid & 31;            // 0..31

    unsigned long long a2[4][8];   // m-packed pairs x 8 n
#pragma unroll
    for (int i = 0; i < 4; i++)
#pragma unroll
        for (int j = 0; j < 8; j++) a2[i][j] = 0ull;

    float4 pf0, pf1, pw0, pw1;

    {
        const int kc = 0;
        pf0 = *(const float4*)(g_fused + (size_t)(m0 + frow0) * FFN + kc + fkq * 4);
        pf1 = *(const float4*)(g_fused + (size_t)(m0 + frow1) * FFN + kc + fkq * 4);
        pw0 = *(const float4*)(Wd + (size_t)(kc + wk0) * DM + n0 + wjq * 4);
        pw1 = *(const float4*)(Wd + (size_t)(kc + wk1) * DM + n0 + wjq * 4);
        fs[0][fkq*4+0][frow0] = pf0.x; fs[0][fkq*4+1][frow0] = pf0.y;
        fs[0][fkq*4+2][frow0] = pf0.z; fs[0][fkq*4+3][frow0] = pf0.w;
        fs[0][fkq*4+0][frow1] = pf1.x; fs[0][fkq*4+1][frow1] = pf1.y;
        fs[0][fkq*4+2][frow1] = pf1.z; fs[0][fkq*4+3][frow1] = pf1.w;
        *(float4*)&wds[0][wk0][wjq*4] = pw0;
        *(float4*)&wds[0][wk1][wjq*4] = pw1;
    }
    __syncthreads();

    for (int ch = 0; ch < 64; ch++) {
        const int p = ch & 1;
        if (ch < 63) {
            const int kc = (ch + 1) * 16;
            pf0 = *(const float4*)(g_fused + (size_t)(m0 + frow0) * FFN + kc + fkq * 4);
            pf1 = *(const float4*)(g_fused + (size_t)(m0 + frow1) * FFN + kc + fkq * 4);
            pw0 = *(const float4*)(Wd + (size_t)(kc + wk0) * DM + n0 + wjq * 4);
            pw1 = *(const float4*)(Wd + (size_t)(kc + wk1) * DM + n0 + wjq * 4);
        }

#pragma unroll
        for (int kk = 0; kk < 16; kk++) {
            const float4 fa0 = *(const float4*)&fs[p][kk][ty * 8];
            const float4 fa1 = *(const float4*)&fs[p][kk][ty * 8 + 4];
            const float4 wa0 = *(const float4*)&wds[p][kk][tx * 4];
            const float4 wa1 = *(const float4*)&wds[p][kk][64 + tx * 4];
            const unsigned long long xp[4] = {
                pack2(fa0.x, fa0.y), pack2(fa0.z, fa0.w),
                pack2(fa1.x, fa1.y), pack2(fa1.z, fa1.w)};
            const float wn[8] = {wa0.x, wa0.y, wa0.z, wa0.w,
                                 wa1.x, wa1.y, wa1.z, wa1.w};
#pragma unroll
            for (int ni = 0; ni < 8; ni++) {
                const unsigned long long wd2 = pack2(wn[ni], wn[ni]);
#pragma unroll
                for (int mp = 0; mp < 4; mp++)
                    a2[mp][ni] = fma2(xp[mp], wd2, a2[mp][ni]);
            }
        }

        if (ch < 63) {
            const int q = 1 - p;
            fs[q][fkq*4+0][frow0] = pf0.x; fs[q][fkq*4+1][frow0] = pf0.y;
            fs[q][fkq*4+2][frow0] = pf0.z; fs[q][fkq*4+3][frow0] = pf0.w;
            fs[q][fkq*4+0][frow1] = pf1.x; fs[q][fkq*4+1][frow1] = pf1.y;
            fs[q][fkq*4+2][frow1] = pf1.z; fs[q][fkq*4+3][frow1] = pf1.w;
            *(float4*)&wds[q][wk0][wjq*4] = pw0;
            *(float4*)&wds[q][wk1][wjq*4] = pw1;
        }
        __syncthreads();
    }

    const float4 bdv0 = *(const float4*)(bd + n0 + tx * 4);
    const float4 bdv1 = *(const float4*)(bd + n0 + 64 + tx * 4);
#pragma unroll
    for (int mp = 0; mp < 4; mp++) {
        float lo[8], hi[8];
#pragma unroll
        for (int ni = 0; ni < 8; ni++) unpack2(a2[mp][ni], lo[ni], hi[ni]);
        float4 o;
        const size_t r0 = (size_t)(m0 + ty * 8 + mp * 2 + 0) * DM;
        const size_t r1 = (size_t)(m0 + ty * 8 + mp * 2 + 1) * DM;
        o.x = lo[0] + bdv0.x; o.y = lo[1] + bdv0.y;
        o.z = lo[2] + bdv0.z; o.w = lo[3] + bdv0.w;
        *(float4*)(out + r0 + n0 + tx * 4) = o;
        o.x = lo[4] + bdv1.x; o.y = lo[5] + bdv1.y;
        o.z = lo[6] + bdv1.z; o.w = lo[7] + bdv1.w;
        *(float4*)(out + r0 + n0 + 64 + tx * 4) = o;
        o.x = hi[0] + bdv0.x; o.y = hi[1] + bdv0.y;
        o.z = hi[2] + bdv0.z; o.w = hi[3] + bdv0.w;
        *(float4*)(out + r1 + n0 + tx * 4) = o;
        o.x = hi[4] + bdv1.x; o.y = hi[5] + bdv1.y;
        o.z = hi[6] + bdv1.z; o.w = hi[7] + bdv1.w;
        *(float4*)(out + r1 + n0 + 64 + tx * 4) = o;
    }
}

extern "C" void kernel_launch(void* const* d_in, const int* in_sizes, int n_in,
                              void* d_out, int out_size) {
    const float* x      = (const float*)d_in[0];
    const float* Wt     = (const float*)d_in[1];
    const float* bt     = (const float*)d_in[2];
    const float* sl_cvx = (const float*)d_in[3];
    const float* of_cvx = (const float*)d_in[4];
    const float* sl_ccv = (const float*)d_in[5];
    const float* of_ccv = (const float*)d_in[6];
    const float* alpha  = (const float*)d_in[7];
    const float* Wc     = (const float*)d_in[8];
    const float* bc     = (const float*)d_in[9];
    const float* Wg     = (const float*)d_in[10];
    const float* bg     = (const float*)d_in[11];
    const float* Wd     = (const float*)d_in[12];
    const float* bd     = (const float*)d_in[13];
    float* out = (float*)d_out;

    dim3 grid1(FFN / 64, T_TOT / 128);   // (16, 256)
    dtn_fused_kernel<<<grid1, 256>>>(x, Wt, bt, sl_cvx, of_cvx, sl_ccv, of_ccv,
                                     alpha, Wc, bc, Wg, bg);

    dim3 grid2(DM / 128, T_TOT / 128);   // (2, 256)
    dtn_out_kernel<<<grid2, 256>>>(Wd, bd, out);
}

// round 5
// speedup vs baseline: 1.0844x; 1.0844x over previous
#include <cuda_runtime.h>
#include <math.h>
#include <stdint.h>

#define T_TOT 32768
#define DM    256
#define FFN   1024

// Scratch (allocation-free rule: __device__ globals)
__device__ float g_xT    [(size_t)DM  * T_TOT];   // x transposed  [256][32768]
__device__ float g_WtT   [(size_t)DM  * FFN];     // Wt transposed [256][1024]
__device__ float g_fusedT[(size_t)FFN * T_TOT];   // fused transposed [1024][32768]

__device__ __forceinline__ float sigf(float z) {
    return 1.0f / (1.0f + __expf(-z));
}

// ---- f32x2 packed-math helpers (sm_103a FFMA2 path) -----------------------
__device__ __forceinline__ unsigned long long pack2(float lo, float hi) {
    unsigned long long r;
    asm("mov.b64 %0, {%1, %2};" : "=l"(r) : "f"(lo), "f"(hi));
    return r;
}
__device__ __forceinline__ void unpack2(unsigned long long v, float& lo, float& hi) {
    asm("mov.b64 {%0, %1}, %2;" : "=f"(lo), "=f"(hi) : "l"(v));
}
__device__ __forceinline__ unsigned long long fma2(unsigned long long a,
                                                   unsigned long long b,
                                                   unsigned long long c) {
    unsigned long long d;
    asm("fma.rn.f32x2 %0, %1, %2, %3;" : "=l"(d) : "l"(a), "l"(b), "l"(c));
    return d;
}
__device__ __forceinline__ unsigned long long add2(unsigned long long a,
                                                   unsigned long long b) {
    unsigned long long d;
    asm("add.rn.f32x2 %0, %1, %2;" : "=l"(d) : "l"(a), "l"(b));
    return d;
}

// ---- cp.async helpers -----------------------------------------------------
__device__ __forceinline__ void cp16(uint32_t smem_addr, const void* gmem) {
    asm volatile("cp.async.cg.shared.global [%0], [%1], 16;"
                 :: "r"(smem_addr), "l"(gmem));
}
__device__ __forceinline__ void cp_commit() {
    asm volatile("cp.async.commit_group;" ::: "memory");
}
template <int N>
__device__ __forceinline__ void cp_wait() {
    asm volatile("cp.async.wait_group %0;" :: "n"(N) : "memory");
}

// ---------------------------------------------------------------------------
// Transpose: in[R][C] -> out[C][R]
// ---------------------------------------------------------------------------
__global__ void transpose_kernel(const float* __restrict__ in,
                                 float* __restrict__ out, int R, int C) {
    __shared__ float t[32][33];
    const int bx = blockIdx.x * 32;  // C offset
    const int by = blockIdx.y * 32;  // R offset
    const int x = threadIdx.x, y = threadIdx.y;  // 32 x 8
#pragma unroll
    for (int i = 0; i < 32; i += 8)
        t[y + i][x] = in[(size_t)(by + y + i) * C + bx + x];
    __syncthreads();
#pragma unroll
    for (int i = 0; i < 32; i += 8)
        out[(size_t)(bx + y + i) * R + by + x] = t[x][y + i];
}

// ---------------------------------------------------------------------------
// Kernel 1: fusedT[j, t] = g*trop + (1-g)*classical  (transposed output)
// Block tile 128 tokens x 64 ffn, 256 threads, per-thread 8m x 4n.
// All smem tiles are direct k-major cp.async copies; double-buffered.
// 2 CTAs/SM.
// smem layout (floats), per buffer row k (stride 336):
//   [0,132)   xs   (128 tokens + pad)
//   [132,200) wts  (64 + pad)
//   [200,268) wcs
//   [268,336) wgs
// ---------------------------------------------------------------------------
#define K1_ROW  336
#define K1_BUF  (16 * K1_ROW)
#define XO      0
#define WTO     132
#define WCO     200
#define WGO     268

__global__ __launch_bounds__(256, 2) void dtn_fused_kernel(
    const float* __restrict__ bt,      // [1024]
    const float* __restrict__ sl_cvx,  // [1024, 8]
    const float* __restrict__ of_cvx,  // [1024, 8]
    const float* __restrict__ sl_ccv,  // [1024, 8]
    const float* __restrict__ of_ccv,  // [1024, 8]
    const float* __restrict__ alpha,   // [1024]
    const float* __restrict__ Wc,      // [256, 1024]
    const float* __restrict__ bc,      // [1024]
    const float* __restrict__ Wg,      // [256, 1024]
    const float* __restrict__ bg)      // [1024]
{
    __shared__ float sm[2 * K1_BUF];   // 43008 B

    const int tid = threadIdx.x;
    const int tx  = tid & 15;   // ffn dir, 4 cols each
    const int ty  = tid >> 4;   // token dir, 8 rows each
    const int m0  = blockIdx.y * 128;
    const int n0  = blockIdx.x * 64;

    const uint32_t smb = (uint32_t)__cvta_generic_to_shared(sm);

    // load indexing
    const int xrow  = tid >> 5;         // 0..7 (row for x, r adds 8)
    const int xcol  = tid & 31;         // 0..31 quads of 4 tokens
    const int wrow  = tid >> 4;         // 0..15 (weight k row)
    const int wcol  = tid & 15;         // 0..15 quads of 4 j

    // gmem base offsets (element index)
    const float* xg  = g_xT + (size_t)xrow * T_TOT + m0 + xcol * 4;
    const float* wtg = g_WtT + (size_t)wrow * FFN + n0 + wcol * 4;
    const float* wcg = Wc    + (size_t)wrow * FFN + n0 + wcol * 4;
    const float* wgg = Wg    + (size_t)wrow * FFN + n0 + wcol * 4;

    const float NEG_INF = __int_as_float(0xff800000);
    float tmax[8][4];
    unsigned long long c2[8][2], g2[8][2];
#pragma unroll
    for (int i = 0; i < 8; i++) {
        c2[i][0] = 0ull; c2[i][1] = 0ull; g2[i][0] = 0ull; g2[i][1] = 0ull;
#pragma unroll
        for (int j = 0; j < 4; j++) tmax[i][j] = NEG_INF;
    }

    // ---- prologue: chunk 0 into buffer 0 ----
    {
        const uint32_t b = smb;
        cp16(b + (uint32_t)((xrow)      * K1_ROW + XO  + xcol * 4) * 4, xg);
        cp16(b + (uint32_t)((xrow + 8)  * K1_ROW + XO  + xcol * 4) * 4, xg + (size_t)8 * T_TOT);
        cp16(b + (uint32_t)(wrow * K1_ROW + WTO + wcol * 4) * 4, wtg);
        cp16(b + (uint32_t)(wrow * K1_ROW + WCO + wcol * 4) * 4, wcg);
        cp16(b + (uint32_t)(wrow * K1_ROW + WGO + wcol * 4) * 4, wgg);
        cp_commit();
    }

    for (int ch = 0; ch < 16; ch++) {
        const int p = ch & 1;
        if (ch < 15) {
            const uint32_t b = smb + (uint32_t)((1 - p) * K1_BUF) * 4;
            const size_t xoff = (size_t)(ch + 1) * 16 * T_TOT;
            const size_t woff = (size_t)(ch + 1) * 16 * FFN;
            cp16(b + (uint32_t)((xrow)     * K1_ROW + XO  + xcol * 4) * 4, xg + xoff);
            cp16(b + (uint32_t)((xrow + 8) * K1_ROW + XO  + xcol * 4) * 4, xg + xoff + (size_t)8 * T_TOT);
            cp16(b + (uint32_t)(wrow * K1_ROW + WTO + wcol * 4) * 4, wtg + woff);
            cp16(b + (uint32_t)(wrow * K1_ROW + WCO + wcol * 4) * 4, wcg + woff);
            cp16(b + (uint32_t)(wrow * K1_ROW + WGO + wcol * 4) * 4, wgg + woff);
            cp_commit();
            cp_wait<1>();
        } else {
            cp_wait<0>();
        }
        __syncthreads();

        const float* buf = sm + p * K1_BUF;
#pragma unroll
        for (int kk = 0; kk < 16; kk++) {
            const float* row = buf + kk * K1_ROW;
            const float4 xa0 = *(const float4*)(row + XO + ty * 8);
            const float4 xa1 = *(const float4*)(row + XO + ty * 8 + 4);
            const float4 wa  = *(const float4*)(row + WTO + tx * 4);
            const float4 ca  = *(const float4*)(row + WCO + tx * 4);
            const float4 ga  = *(const float4*)(row + WGO + tx * 4);
            const float xm[8] = {xa0.x, xa0.y, xa0.z, xa0.w,
                                 xa1.x, xa1.y, xa1.z, xa1.w};
            const unsigned long long wp[2] = {pack2(wa.x, wa.y), pack2(wa.z, wa.w)};
            const unsigned long long cp[2] = {pack2(ca.x, ca.y), pack2(ca.z, ca.w)};
            const unsigned long long gp[2] = {pack2(ga.x, ga.y), pack2(ga.z, ga.w)};
#pragma unroll
            for (int mi = 0; mi < 8; mi++) {
                const unsigned long long xd = pack2(xm[mi], xm[mi]);
#pragma unroll
                for (int pp = 0; pp < 2; pp++) {
                    c2[mi][pp] = fma2(xd, cp[pp], c2[mi][pp]);
                    g2[mi][pp] = fma2(xd, gp[pp], g2[mi][pp]);
                    const unsigned long long t2 = add2(xd, wp[pp]);
                    float tlo, thi;
                    unpack2(t2, tlo, thi);
                    tmax[mi][2*pp+0] = fmaxf(tmax[mi][2*pp+0], tlo);
                    tmax[mi][2*pp+1] = fmaxf(tmax[mi][2*pp+1], thi);
                }
            }
        }
        __syncthreads();
    }

    // ---- epilogue: compute fused, stage transposed in smem, write fusedT --
    // staging: ts[j_local][m_local], row stride 132 floats (reuses sm[])
#pragma unroll
    for (int ni = 0; ni < 4; ni++) {
        const int j = n0 + tx * 4 + ni;
        const float btj = bt[j];
        const float s   = sigf(alpha[j]);
        const float bcj = bc[j];
        const float bgj = bg[j];
        const float4 sc0 = *(const float4*)(sl_cvx + (size_t)j * 8);
        const float4 sc1 = *(const float4*)(sl_cvx + (size_t)j * 8 + 4);
        const float4 oc0 = *(const float4*)(of_cvx + (size_t)j * 8);
        const float4 oc1 = *(const float4*)(of_cvx + (size_t)j * 8 + 4);
        const float4 sv0 = *(const float4*)(sl_ccv + (size_t)j * 8);
        const float4 sv1 = *(const float4*)(sl_ccv + (size_t)j * 8 + 4);
        const float4 ov0 = *(const float4*)(of_ccv + (size_t)j * 8);
        const float4 ov1 = *(const float4*)(of_ccv + (size_t)j * 8 + 4);
#pragma unroll
        for (int mi = 0; mi < 8; mi++) {
            float clo, chi, glo, ghi;
            unpack2(c2[mi][ni >> 1], clo, chi);
            unpack2(g2[mi][ni >> 1], glo, ghi);
            const float accc = (ni & 1) ? chi : clo;
            const float accg = (ni & 1) ? ghi : glo;

            const float t = tmax[mi][ni] + btj;
            float cvx = fmaf(t, sc0.x, oc0.x);
            cvx = fmaxf(cvx, fmaf(t, sc0.y, oc0.y));
            cvx = fmaxf(cvx, fmaf(t, sc0.z, oc0.z));
            cvx = fmaxf(cvx, fmaf(t, sc0.w, oc0.w));
            cvx = fmaxf(cvx, fmaf(t, sc1.x, oc1.x));
            cvx = fmaxf(cvx, fmaf(t, sc1.y, oc1.y));
            cvx = fmaxf(cvx, fmaf(t, sc1.z, oc1.z));
            cvx = fmaxf(cvx, fmaf(t, sc1.w, oc1.w));
            float ccv = fmaf(t, sv0.x, ov0.x);
            ccv = fminf(ccv, fmaf(t, sv0.y, ov0.y));
            ccv = fminf(ccv, fmaf(t, sv0.z, ov0.z));
            ccv = fminf(ccv, fmaf(t, sv0.w, ov0.w));
            ccv = fminf(ccv, fmaf(t, sv1.x, ov1.x));
            ccv = fminf(ccv, fmaf(t, sv1.y, ov1.y));
            ccv = fminf(ccv, fmaf(t, sv1.z, ov1.z));
            ccv = fminf(ccv, fmaf(t, sv1.w, ov1.w));
            const float trop = s * cvx + (1.0f - s) * ccv;

            const float v   = accc + bcj;
            const float cls = 0.5f * v * (1.0f + erff(v * 0.70710678118654752f));
            const float g   = sigf(accg + bgj);

            sm[(tx * 4 + ni) * 132 + ty * 8 + mi] = g * trop + (1.0f - g) * cls;
        }
    }
    __syncthreads();

    // write out: 64 rows x 128 tokens, coalesced float4
#pragma unroll
    for (int r = 0; r < 8; r++) {
        const int idx = tid + r * 256;
        const int row = idx >> 5;       // 0..63
        const int c   = idx & 31;       // 0..31
        *(float4*)(g_fusedT + (size_t)(n0 + row) * T_TOT + m0 + c * 4) =
            *(const float4*)(sm + row * 132 + c * 4);
    }
}

// ---------------------------------------------------------------------------
// Kernel 2: out[T, 256] = fusedT^T @ Wd + bd
// Block tile 128 x 128, 256 threads, per-thread 8m x 8n, m-packed FMA2.
// All-cp.async double-buffered. 2 CTAs/SM.
// smem row k (stride 264): [0,132) fs (tokens), [132,264) wds
// ---------------------------------------------------------------------------
#define K2_ROW 264
#define K2_BUF (16 * K2_ROW)
#define FO     0
#define WDO    132

__global__ __launch_bounds__(256, 2) void dtn_out_kernel(
    const float* __restrict__ Wd,      // [1024, 256]
    const float* __restrict__ bd,      // [256]
    float* __restrict__ out)           // [T, 256]
{
    __shared__ float sm[2 * K2_BUF];   // 33792 B

    const int tid = threadIdx.x;
    const int tx  = tid & 15;
    const int ty  = tid >> 4;
    const int m0  = blockIdx.y * 128;
    const int n0  = blockIdx.x * 128;

    const uint32_t smb = (uint32_t)__cvta_generic_to_shared(sm);

    const int lrow = tid >> 5;          // 0..7
    const int lcol = tid & 31;          // 0..31

    const float* fg = g_fusedT + (size_t)lrow * T_TOT + m0 + lcol * 4;
    const float* wg = Wd       + (size_t)lrow * DM   + n0 + lcol * 4;

    unsigned long long a2[4][8];
#pragma unroll
    for (int i = 0; i < 4; i++)
#pragma unroll
        for (int j = 0; j < 8; j++) a2[i][j] = 0ull;

    {
        const uint32_t b = smb;
        cp16(b + (uint32_t)((lrow)     * K2_ROW + FO  + lcol * 4) * 4, fg);
        cp16(b + (uint32_t)((lrow + 8) * K2_ROW + FO  + lcol * 4) * 4, fg + (size_t)8 * T_TOT);
        cp16(b + (uint32_t)((lrow)     * K2_ROW + WDO + lcol * 4) * 4, wg);
        cp16(b + (uint32_t)((lrow + 8) * K2_ROW + WDO + lcol * 4) * 4, wg + (size_t)8 * DM);
        cp_commit();
    }

    for (int ch = 0; ch < 64; ch++) {
        const int p = ch & 1;
        if (ch < 63) {
            const uint32_t b = smb + (uint32_t)((1 - p) * K2_BUF) * 4;
            const size_t foff = (size_t)(ch + 1) * 16 * T_TOT;
            const size_t woff = (size_t)(ch + 1) * 16 * DM;
            cp16(b + (uint32_t)((lrow)     * K2_ROW + FO  + lcol * 4) * 4, fg + foff);
            cp16(b + (uint32_t)((lrow + 8) * K2_ROW + FO  + lcol * 4) * 4, fg + foff + (size_t)8 * T_TOT);
            cp16(b + (uint32_t)((lrow)     * K2_ROW + WDO + lcol * 4) * 4, wg + woff);
            cp16(b + (uint32_t)((lrow + 8) * K2_ROW + WDO + lcol * 4) * 4, wg + woff + (size_t)8 * DM);
            cp_commit();
            cp_wait<1>();
        } else {
            cp_wait<0>();
        }
        __syncthreads();

        const float* buf = sm + p * K2_BUF;
#pragma unroll
        for (int kk = 0; kk < 16; kk++) {
            const float* row = buf + kk * K2_ROW;
            const float4 fa0 = *(const float4*)(row + FO + ty * 8);
            const float4 fa1 = *(const float4*)(row + FO + ty * 8 + 4);
            const float4 wa0 = *(const float4*)(row + WDO + tx * 4);
            const float4 wa1 = *(const float4*)(row + WDO + 64 + tx * 4);
            const unsigned long long xp[4] = {
                pack2(fa0.x, fa0.y), pack2(fa0.z, fa0.w),
                pack2(fa1.x, fa1.y), pack2(fa1.z, fa1.w)};
            const float wn[8] = {wa0.x, wa0.y, wa0.z, wa0.w,
                                 wa1.x, wa1.y, wa1.z, wa1.w};
#pragma unroll
            for (int ni = 0; ni < 8; ni++) {
                const unsigned long long wd2 = pack2(wn[ni], wn[ni]);
#pragma unroll
                for (int mp = 0; mp < 4; mp++)
                    a2[mp][ni] = fma2(xp[mp], wd2, a2[mp][ni]);
            }
        }
        __syncthreads();
    }

    const float4 bdv0 = *(const float4*)(bd + n0 + tx * 4);
    const float4 bdv1 = *(const float4*)(bd + n0 + 64 + tx * 4);
#pragma unroll
    for (int mp = 0; mp < 4; mp++) {
        float lo[8], hi[8];
#pragma unroll
        for (int ni = 0; ni < 8; ni++) unpack2(a2[mp][ni], lo[ni], hi[ni]);
        float4 o;
        const size_t r0 = (size_t)(m0 + ty * 8 + mp * 2 + 0) * DM;
        const size_t r1 = (size_t)(m0 + ty * 8 + mp * 2 + 1) * DM;
        o.x = lo[0] + bdv0.x; o.y = lo[1] + bdv0.y;
        o.z = lo[2] + bdv0.z; o.w = lo[3] + bdv0.w;
        *(float4*)(out + r0 + n0 + tx * 4) = o;
        o.x = lo[4] + bdv1.x; o.y = lo[5] + bdv1.y;
        o.z = lo[6] + bdv1.z; o.w = lo[7] + bdv1.w;
        *(float4*)(out + r0 + n0 + 64 + tx * 4) = o;
        o.x = hi[0] + bdv0.x; o.y = hi[1] + bdv0.y;
        o.z = hi[2] + bdv0.z; o.w = hi[3] + bdv0.w;
        *(float4*)(out + r1 + n0 + tx * 4) = o;
        o.x = hi[4] + bdv1.x; o.y = hi[5] + bdv1.y;
        o.z = hi[6] + bdv1.z; o.w = hi[7] + bdv1.w;
        *(float4*)(out + r1 + n0 + 64 + tx * 4) = o;
    }
}

extern "C" void kernel_launch(void* const* d_in, const int* in_sizes, int n_in,
                              void* d_out, int out_size) {
    const float* x      = (const float*)d_in[0];
    const float* Wt     = (const float*)d_in[1];
    const float* bt     = (const float*)d_in[2];
    const float* sl_cvx = (const float*)d_in[3];
    const float* of_cvx = (const float*)d_in[4];
    const float* sl_ccv = (const float*)d_in[5];
    const float* of_ccv = (const float*)d_in[6];
    const float* alpha  = (const float*)d_in[7];
    const float* Wc     = (const float*)d_in[8];
    const float* bc     = (const float*)d_in[9];
    const float* Wg     = (const float*)d_in[10];
    const float* bg     = (const float*)d_in[11];
    const float* Wd     = (const float*)d_in[12];
    const float* bd     = (const float*)d_in[13];
    float* out = (float*)d_out;

    float* xT;  cudaGetSymbolAddress((void**)&xT,  g_xT);
    float* wtT; cudaGetSymbolAddress((void**)&wtT, g_WtT);

    // x [32768,256] -> xT [256][32768]
    transpose_kernel<<<dim3(DM / 32, T_TOT / 32), dim3(32, 8)>>>(x, xT, T_TOT, DM);
    // Wt [1024,256] -> WtT [256][1024]
    transpose_kernel<<<dim3(DM / 32, FFN / 32), dim3(32, 8)>>>(Wt, wtT, FFN, DM);

    dim3 grid1(FFN / 64, T_TOT / 128);   // (16, 256)
    dtn_fused_kernel<<<grid1, 256>>>(bt, sl_cvx, of_cvx, sl_ccv, of_ccv,
                                     alpha, Wc, bc, Wg, bg);

    dim3 grid2(DM / 128, T_TOT / 128);   // (2, 256)
    dtn_out_kernel<<<grid2, 256>>>(Wd, bd, out);
}

// round 6
// speedup vs baseline: 1.0853x; 1.0009x over previous
#include <cuda_runtime.h>
#include <math.h>
#include <stdint.h>

#define T_TOT 32768
#define DM    256
#define FFN   1024

// Scratch (allocation-free rule: __device__ globals)
__device__ float g_xT    [(size_t)DM  * T_TOT];   // x transposed  [256][32768]
__device__ float g_WtT   [(size_t)DM  * FFN];     // Wt transposed [256][1024]
__device__ float g_fusedT[(size_t)FFN * T_TOT];   // fused transposed [1024][32768]

__device__ __forceinline__ float sigf(float z) {
    return 1.0f / (1.0f + __expf(-z));
}

// ---- f32x2 packed-math helpers (sm_103a FFMA2 path) -----------------------
__device__ __forceinline__ unsigned long long pack2(float lo, float hi) {
    unsigned long long r;
    asm("mov.b64 %0, {%1, %2};" : "=l"(r) : "f"(lo), "f"(hi));
    return r;
}
__device__ __forceinline__ void unpack2(unsigned long long v, float& lo, float& hi) {
    asm("mov.b64 {%0, %1}, %2;" : "=f"(lo), "=f"(hi) : "l"(v));
}
__device__ __forceinline__ unsigned long long fma2(unsigned long long a,
                                                   unsigned long long b,
                                                   unsigned long long c) {
    unsigned long long d;
    asm("fma.rn.f32x2 %0, %1, %2, %3;" : "=l"(d) : "l"(a), "l"(b), "l"(c));
    return d;
}
__device__ __forceinline__ unsigned long long add2(unsigned long long a,
                                                   unsigned long long b) {
    unsigned long long d;
    asm("add.rn.f32x2 %0, %1, %2;" : "=l"(d) : "l"(a), "l"(b));
    return d;
}

// ---- cp.async helpers -----------------------------------------------------
__device__ __forceinline__ void cp16(uint32_t smem_addr, const void* gmem) {
    asm volatile("cp.async.cg.shared.global [%0], [%1], 16;"
                 :: "r"(smem_addr), "l"(gmem));
}
__device__ __forceinline__ void cp_commit() {
    asm volatile("cp.async.commit_group;" ::: "memory");
}
template <int N>
__device__ __forceinline__ void cp_wait() {
    asm volatile("cp.async.wait_group %0;" :: "n"(N) : "memory");
}

// ---------------------------------------------------------------------------
// Transpose: in[R][C] -> out[C][R]
// ---------------------------------------------------------------------------
__global__ void transpose_kernel(const float* __restrict__ in,
                                 float* __restrict__ out, int R, int C) {
    __shared__ float t[32][33];
    const int bx = blockIdx.x * 32;  // C offset
    const int by = blockIdx.y * 32;  // R offset
    const int x = threadIdx.x, y = threadIdx.y;  // 32 x 8
#pragma unroll
    for (int i = 0; i < 32; i += 8)
        t[y + i][x] = in[(size_t)(by + y + i) * C + bx + x];
    __syncthreads();
#pragma unroll
    for (int i = 0; i < 32; i += 8)
        out[(size_t)(bx + y + i) * R + by + x] = t[x][y + i];
}

// ---------------------------------------------------------------------------
// Kernel 1: fusedT[j, t] = g*trop + (1-g)*classical  (transposed output)
// Block tile 128 tokens x 64 ffn, 256 threads, per-thread 8m x 4n.
// All smem tiles are direct k-major cp.async copies; double-buffered.
// 2 CTAs/SM.
// smem layout (floats), per buffer row k (stride 336):
//   [0,132)   xs   (128 tokens + pad)
//   [132,200) wts  (64 + pad)
//   [200,268) wcs
//   [268,336) wgs
// ---------------------------------------------------------------------------
#define K1_ROW  336
#define K1_BUF  (16 * K1_ROW)
#define XO      0
#define WTO     132
#define WCO     200
#define WGO     268

__global__ __launch_bounds__(256, 2) void dtn_fused_kernel(
    const float* __restrict__ bt,      // [1024]
    const float* __restrict__ sl_cvx,  // [1024, 8]
    const float* __restrict__ of_cvx,  // [1024, 8]
    const float* __restrict__ sl_ccv,  // [1024, 8]
    const float* __restrict__ of_ccv,  // [1024, 8]
    const float* __restrict__ alpha,   // [1024]
    const float* __restrict__ Wc,      // [256, 1024]
    const float* __restrict__ bc,      // [1024]
    const float* __restrict__ Wg,      // [256, 1024]
    const float* __restrict__ bg)      // [1024]
{
    __shared__ float sm[2 * K1_BUF];   // 43008 B

    const int tid = threadIdx.x;
    const int tx  = tid & 15;   // ffn dir, 4 cols each
    const int ty  = tid >> 4;   // token dir, 8 rows each
    const int m0  = blockIdx.y * 128;
    const int n0  = blockIdx.x * 64;

    const uint32_t smb = (uint32_t)__cvta_generic_to_shared(sm);

    // load indexing
    const int xrow  = tid >> 5;         // 0..7 (row for x, r adds 8)
    const int xcol  = tid & 31;         // 0..31 quads of 4 tokens
    const int wrow  = tid >> 4;         // 0..15 (weight k row)
    const int wcol  = tid & 15;         // 0..15 quads of 4 j

    // gmem base offsets (element index)
    const float* xg  = g_xT + (size_t)xrow * T_TOT + m0 + xcol * 4;
    const float* wtg = g_WtT + (size_t)wrow * FFN + n0 + wcol * 4;
    const float* wcg = Wc    + (size_t)wrow * FFN + n0 + wcol * 4;
    const float* wgg = Wg    + (size_t)wrow * FFN + n0 + wcol * 4;

    const float NEG_INF = __int_as_float(0xff800000);
    float tmax[8][4];
    unsigned long long c2[8][2], g2[8][2];
#pragma unroll
    for (int i = 0; i < 8; i++) {
        c2[i][0] = 0ull; c2[i][1] = 0ull; g2[i][0] = 0ull; g2[i][1] = 0ull;
#pragma unroll
        for (int j = 0; j < 4; j++) tmax[i][j] = NEG_INF;
    }

    // ---- prologue: chunk 0 into buffer 0 ----
    {
        const uint32_t b = smb;
        cp16(b + (uint32_t)((xrow)      * K1_ROW + XO  + xcol * 4) * 4, xg);
        cp16(b + (uint32_t)((xrow + 8)  * K1_ROW + XO  + xcol * 4) * 4, xg + (size_t)8 * T_TOT);
        cp16(b + (uint32_t)(wrow * K1_ROW + WTO + wcol * 4) * 4, wtg);
        cp16(b + (uint32_t)(wrow * K1_ROW + WCO + wcol * 4) * 4, wcg);
        cp16(b + (uint32_t)(wrow * K1_ROW + WGO + wcol * 4) * 4, wgg);
        cp_commit();
    }

    for (int ch = 0; ch < 16; ch++) {
        const int p = ch & 1;
        if (ch < 15) {
            const uint32_t b = smb + (uint32_t)((1 - p) * K1_BUF) * 4;
            const size_t xoff = (size_t)(ch + 1) * 16 * T_TOT;
            const size_t woff = (size_t)(ch + 1) * 16 * FFN;
            cp16(b + (uint32_t)((xrow)     * K1_ROW + XO  + xcol * 4) * 4, xg + xoff);
            cp16(b + (uint32_t)((xrow + 8) * K1_ROW + XO  + xcol * 4) * 4, xg + xoff + (size_t)8 * T_TOT);
            cp16(b + (uint32_t)(wrow * K1_ROW + WTO + wcol * 4) * 4, wtg + woff);
            cp16(b + (uint32_t)(wrow * K1_ROW + WCO + wcol * 4) * 4, wcg + woff);
            cp16(b + (uint32_t)(wrow * K1_ROW + WGO + wcol * 4) * 4, wgg + woff);
            cp_commit();
            cp_wait<1>();
        } else {
            cp_wait<0>();
        }
        __syncthreads();

        const float* buf = sm + p * K1_BUF;
#pragma unroll
        for (int kk = 0; kk < 16; kk++) {
            const float* row = buf + kk * K1_ROW;
            const float4 xa0 = *(const float4*)(row + XO + ty * 8);
            const float4 xa1 = *(const float4*)(row + XO + ty * 8 + 4);
            const float4 wa  = *(const float4*)(row + WTO + tx * 4);
            const float4 ca  = *(const float4*)(row + WCO + tx * 4);
            const float4 ga  = *(const float4*)(row + WGO + tx * 4);
            const float xm[8] = {xa0.x, xa0.y, xa0.z, xa0.w,
                                 xa1.x, xa1.y, xa1.z, xa1.w};
            const unsigned long long wp[2] = {pack2(wa.x, wa.y), pack2(wa.z, wa.w)};
            const unsigned long long cp[2] = {pack2(ca.x, ca.y), pack2(ca.z, ca.w)};
            const unsigned long long gp[2] = {pack2(ga.x, ga.y), pack2(ga.z, ga.w)};
#pragma unroll
            for (int mi = 0; mi < 8; mi++) {
                const unsigned long long xd = pack2(xm[mi], xm[mi]);
#pragma unroll
                for (int pp = 0; pp < 2; pp++) {
                    c2[mi][pp] = fma2(xd, cp[pp], c2[mi][pp]);
                    g2[mi][pp] = fma2(xd, gp[pp], g2[mi][pp]);
                    const unsigned long long t2 = add2(xd, wp[pp]);
                    float tlo, thi;
                    unpack2(t2, tlo, thi);
                    tmax[mi][2*pp+0] = fmaxf(tmax[mi][2*pp+0], tlo);
                    tmax[mi][2*pp+1] = fmaxf(tmax[mi][2*pp+1], thi);
                }
            }
        }
        __syncthreads();
    }

    // ---- epilogue: compute fused, stage transposed in smem, write fusedT --
    // staging: ts[j_local][m_local], row stride 132 floats (reuses sm[])
#pragma unroll
    for (int ni = 0; ni < 4; ni++) {
        const int j = n0 + tx * 4 + ni;
        const float btj = bt[j];
        const float s   = sigf(alpha[j]);
        const float bcj = bc[j];
        const float bgj = bg[j];
        const float4 sc0 = *(const float4*)(sl_cvx + (size_t)j * 8);
        const float4 sc1 = *(const float4*)(sl_cvx + (size_t)j * 8 + 4);
        const float4 oc0 = *(const float4*)(of_cvx + (size_t)j * 8);
        const float4 oc1 = *(const float4*)(of_cvx + (size_t)j * 8 + 4);
        const float4 sv0 = *(const float4*)(sl_ccv + (size_t)j * 8);
        const float4 sv1 = *(const float4*)(sl_ccv + (size_t)j * 8 + 4);
        const float4 ov0 = *(const float4*)(of_ccv + (size_t)j * 8);
        const float4 ov1 = *(const float4*)(of_ccv + (size_t)j * 8 + 4);
#pragma unroll
        for (int mi = 0; mi < 8; mi++) {
            float clo, chi, glo, ghi;
            unpack2(c2[mi][ni >> 1], clo, chi);
            unpack2(g2[mi][ni >> 1], glo, ghi);
            const float accc = (ni & 1) ? chi : clo;
            const float accg = (ni & 1) ? ghi : glo;

            const float t = tmax[mi][ni] + btj;
            float cvx = fmaf(t, sc0.x, oc0.x);
            cvx = fmaxf(cvx, fmaf(t, sc0.y, oc0.y));
            cvx = fmaxf(cvx, fmaf(t, sc0.z, oc0.z));
            cvx = fmaxf(cvx, fmaf(t, sc0.w, oc0.w));
            cvx = fmaxf(cvx, fmaf(t, sc1.x, oc1.x));
            cvx = fmaxf(cvx, fmaf(t, sc1.y, oc1.y));
            cvx = fmaxf(cvx, fmaf(t, sc1.z, oc1.z));
            cvx = fmaxf(cvx, fmaf(t, sc1.w, oc1.w));
            float ccv = fmaf(t, sv0.x, ov0.x);
            ccv = fminf(ccv, fmaf(t, sv0.y, ov0.y));
            ccv = fminf(ccv, fmaf(t, sv0.z, ov0.z));
            ccv = fminf(ccv, fmaf(t, sv0.w, ov0.w));
            ccv = fminf(ccv, fmaf(t, sv1.x, ov1.x));
            ccv = fminf(ccv, fmaf(t, sv1.y, ov1.y));
            ccv = fminf(ccv, fmaf(t, sv1.z, ov1.z));
            ccv = fminf(ccv, fmaf(t, sv1.w, ov1.w));
            const float trop = s * cvx + (1.0f - s) * ccv;

            const float v   = accc + bcj;
            const float cls = 0.5f * v * (1.0f + erff(v * 0.70710678118654752f));
            const float g   = sigf(accg + bgj);

            sm[(tx * 4 + ni) * 132 + ty * 8 + mi] = g * trop + (1.0f - g) * cls;
        }
    }
    __syncthreads();

    // write out: 64 rows x 128 tokens, coalesced float4
#pragma unroll
    for (int r = 0; r < 8; r++) {
        const int idx = tid + r * 256;
        const int row = idx >> 5;       // 0..63
        const int c   = idx & 31;       // 0..31
        *(float4*)(g_fusedT + (size_t)(n0 + row) * T_TOT + m0 + c * 4) =
            *(const float4*)(sm + row * 132 + c * 4);
    }
}

// ---------------------------------------------------------------------------
// Kernel 2: out[T, 256] = fusedT^T @ Wd + bd
// Block tile 128 x 128, 256 threads, per-thread 8m x 8n, m-packed FMA2.
// All-cp.async double-buffered. 2 CTAs/SM.
// smem row k (stride 264): [0,132) fs (tokens), [132,264) wds
// ---------------------------------------------------------------------------
#define K2_ROW 264
#define K2_BUF (16 * K2_ROW)
#define FO     0
#define WDO    132

__global__ __launch_bounds__(256, 2) void dtn_out_kernel(
    const float* __restrict__ Wd,      // [1024, 256]
    const float* __restrict__ bd,      // [256]
    float* __restrict__ out)           // [T, 256]
{
    __shared__ float sm[2 * K2_BUF];   // 33792 B

    const int tid = threadIdx.x;
    const int tx  = tid & 15;
    const int ty  = tid >> 4;
    const int m0  = blockIdx.y * 128;
    const int n0  = blockIdx.x * 128;

    const uint32_t smb = (uint32_t)__cvta_generic_to_shared(sm);

    const int lrow = tid >> 5;          // 0..7
    const int lcol = tid & 31;          // 0..31

    const float* fg = g_fusedT + (size_t)lrow * T_TOT + m0 + lcol * 4;
    const float* wg = Wd       + (size_t)lrow * DM   + n0 + lcol * 4;

    unsigned long long a2[4][8];
#pragma unroll
    for (int i = 0; i < 4; i++)
#pragma unroll
        for (int j = 0; j < 8; j++) a2[i][j] = 0ull;

    {
        const uint32_t b = smb;
        cp16(b + (uint32_t)((lrow)     * K2_ROW + FO  + lcol * 4) * 4, fg);
        cp16(b + (uint32_t)((lrow + 8) * K2_ROW + FO  + lcol * 4) * 4, fg + (size_t)8 * T_TOT);
        cp16(b + (uint32_t)((lrow)     * K2_ROW + WDO + lcol * 4) * 4, wg);
        cp16(b + (uint32_t)((lrow + 8) * K2_ROW + WDO + lcol * 4) * 4, wg + (size_t)8 * DM);
        cp_commit();
    }

    for (int ch = 0; ch < 64; ch++) {
        const int p = ch & 1;
        if (ch < 63) {
            const uint32_t b = smb + (uint32_t)((1 - p) * K2_BUF) * 4;
            const size_t foff = (size_t)(ch + 1) * 16 * T_TOT;
            const size_t woff = (size_t)(ch + 1) * 16 * DM;
            cp16(b + (uint32_t)((lrow)     * K2_ROW + FO  + lcol * 4) * 4, fg + foff);
            cp16(b + (uint32_t)((lrow + 8) * K2_ROW + FO  + lcol * 4) * 4, fg + foff + (size_t)8 * T_TOT);
            cp16(b + (uint32_t)((lrow)     * K2_ROW + WDO + lcol * 4) * 4, wg + woff);
            cp16(b + (uint32_t)((lrow + 8) * K2_ROW + WDO + lcol * 4) * 4, wg + woff + (size_t)8 * DM);
            cp_commit();
            cp_wait<1>();
        } else {
            cp_wait<0>();
        }
        __syncthreads();

        const float* buf = sm + p * K2_BUF;
#pragma unroll
        for (int kk = 0; kk < 16; kk++) {
            const float* row = buf + kk * K2_ROW;
            const float4 fa0 = *(const float4*)(row + FO + ty * 8);
            const float4 fa1 = *(const float4*)(row + FO + ty * 8 + 4);
            const float4 wa0 = *(const float4*)(row + WDO + tx * 4);
            const float4 wa1 = *(const float4*)(row + WDO + 64 + tx * 4);
            const unsigned long long xp[4] = {
                pack2(fa0.x, fa0.y), pack2(fa0.z, fa0.w),
                pack2(fa1.x, fa1.y), pack2(fa1.z, fa1.w)};
            const float wn[8] = {wa0.x, wa0.y, wa0.z, wa0.w,
                                 wa1.x, wa1.y, wa1.z, wa1.w};
#pragma unroll
            for (int ni = 0; ni < 8; ni++) {
                const unsigned long long wd2 = pack2(wn[ni], wn[ni]);
#pragma unroll
                for (int mp = 0; mp < 4; mp++)
                    a2[mp][ni] = fma2(xp[mp], wd2, a2[mp][ni]);
            }
        }
        __syncthreads();
    }

    const float4 bdv0 = *(const float4*)(bd + n0 + tx * 4);
    const float4 bdv1 = *(const float4*)(bd + n0 + 64 + tx * 4);
#pragma unroll
    for (int mp = 0; mp < 4; mp++) {
        float lo[8], hi[8];
#pragma unroll
        for (int ni = 0; ni < 8; ni++) unpack2(a2[mp][ni], lo[ni], hi[ni]);
        float4 o;
        const size_t r0 = (size_t)(m0 + ty * 8 + mp * 2 + 0) * DM;
        const size_t r1 = (size_t)(m0 + ty * 8 + mp * 2 + 1) * DM;
        o.x = lo[0] + bdv0.x; o.y = lo[1] + bdv0.y;
        o.z = lo[2] + bdv0.z; o.w = lo[3] + bdv0.w;
        *(float4*)(out + r0 + n0 + tx * 4) = o;
        o.x = lo[4] + bdv1.x; o.y = lo[5] + bdv1.y;
        o.z = lo[6] + bdv1.z; o.w = lo[7] + bdv1.w;
        *(float4*)(out + r0 + n0 + 64 + tx * 4) = o;
        o.x = hi[0] + bdv0.x; o.y = hi[1] + bdv0.y;
        o.z = hi[2] + bdv0.z; o.w = hi[3] + bdv0.w;
        *(float4*)(out + r1 + n0 + tx * 4) = o;
        o.x = hi[4] + bdv1.x; o.y = hi[5] + bdv1.y;
        o.z = hi[6] + bdv1.z; o.w = hi[7] + bdv1.w;
        *(float4*)(out + r1 + n0 + 64 + tx * 4) = o;
    }
}

extern "C" void kernel_launch(void* const* d_in, const int* in_sizes, int n_in,
                              void* d_out, int out_size) {
    const float* x      = (const float*)d_in[0];
    const float* Wt     = (const float*)d_in[1];
    const float* bt     = (const float*)d_in[2];
    const float* sl_cvx = (const float*)d_in[3];
    const float* of_cvx = (const float*)d_in[4];
    const float* sl_ccv = (const float*)d_in[5];
    const float* of_ccv = (const float*)d_in[6];
    const float* alpha  = (const float*)d_in[7];
    const float* Wc     = (const float*)d_in[8];
    const float* bc     = (const float*)d_in[9];
    const float* Wg     = (const float*)d_in[10];
    const float* bg     = (const float*)d_in[11];
    const float* Wd     = (const float*)d_in[12];
    const float* bd     = (const float*)d_in[13];
    float* out = (float*)d_out;

    float* xT;  cudaGetSymbolAddress((void**)&xT,  g_xT);
    float* wtT; cudaGetSymbolAddress((void**)&wtT, g_WtT);

    // x [32768,256] -> xT [256][32768]
    transpose_kernel<<<dim3(DM / 32, T_TOT / 32), dim3(32, 8)>>>(x, xT, T_TOT, DM);
    // Wt [1024,256] -> WtT [256][1024]
    transpose_kernel<<<dim3(DM / 32, FFN / 32), dim3(32, 8)>>>(Wt, wtT, FFN, DM);

    dim3 grid1(FFN / 64, T_TOT / 128);   // (16, 256)
    dtn_fused_kernel<<<grid1, 256>>>(bt, sl_cvx, of_cvx, sl_ccv, of_ccv,
                                     alpha, Wc, bc, Wg, bg);

    dim3 grid2(DM / 128, T_TOT / 128);   // (2, 256)
    dtn_out_kernel<<<grid2, 256>>>(Wd, bd, out);
}

// round 8
// speedup vs baseline: 1.1416x; 1.0519x over previous
#include <cuda_runtime.h>
#include <cuda_bf16.h>
#include <math.h>
#include <stdint.h>

#define T_TOT 32768
#define DM    256
#define FFN   1024

// ---------------- scratch (allocation-free rule) ---------------------------
__device__ float g_xT  [(size_t)DM * T_TOT];      // x^T [256][32768] fp32
__device__ float g_WtT [(size_t)DM * FFN];        // Wt^T [256][1024] fp32
__device__ float g_tT  [(size_t)FFN * T_TOT];     // tropical+bt [1024][32768]
__device__ float g_fusedT[(size_t)FFN * T_TOT];   // fused [1024][32768]
__device__ __nv_bfloat16 g_xh [(size_t)T_TOT * DM];  // x hi [32768][256]
__device__ __nv_bfloat16 g_xl [(size_t)T_TOT * DM];
__device__ __nv_bfloat16 g_Wch[(size_t)FFN * DM];    // Wc^T hi [1024][256]
__device__ __nv_bfloat16 g_Wcl[(size_t)FFN * DM];
__device__ __nv_bfloat16 g_Wgh[(size_t)FFN * DM];
__device__ __nv_bfloat16 g_Wgl[(size_t)FFN * DM];

__device__ __forceinline__ float sigf(float z) { return 1.0f / (1.0f + __expf(-z)); }
__device__ __forceinline__ unsigned long long pack2(float lo, float hi) {
    unsigned long long r; asm("mov.b64 %0, {%1, %2};" : "=l"(r) : "f"(lo), "f"(hi)); return r;
}
__device__ __forceinline__ void unpack2(unsigned long long v, float& lo, float& hi) {
    asm("mov.b64 {%0, %1}, %2;" : "=f"(lo), "=f"(hi) : "l"(v));
}
__device__ __forceinline__ unsigned long long add2(unsigned long long a, unsigned long long b) {
    unsigned long long d; asm("add.rn.f32x2 %0, %1, %2;" : "=l"(d) : "l"(a), "l"(b)); return d;
}
__device__ __forceinline__ unsigned long long fma2(unsigned long long a, unsigned long long b, unsigned long long c) {
    unsigned long long d; asm("fma.rn.f32x2 %0, %1, %2, %3;" : "=l"(d) : "l"(a), "l"(b), "l"(c)); return d;
}
__device__ __forceinline__ void cp16(uint32_t s, const void* g) {
    asm volatile("cp.async.cg.shared.global [%0], [%1], 16;" :: "r"(s), "l"(g));
}
__device__ __forceinline__ void cp_commit() { asm volatile("cp.async.commit_group;" ::: "memory"); }
template <int N> __device__ __forceinline__ void cp_wait() {
    asm volatile("cp.async.wait_group %0;" :: "n"(N) : "memory");
}
__device__ __forceinline__ void ldsm4(uint32_t* r, uint32_t a) {
    asm volatile("ldmatrix.sync.aligned.m8n8.x4.shared.b16 {%0,%1,%2,%3}, [%4];"
                 : "=r"(r[0]), "=r"(r[1]), "=r"(r[2]), "=r"(r[3]) : "r"(a));
}
__device__ __forceinline__ void ldsm2(uint32_t* r, uint32_t a) {
    asm volatile("ldmatrix.sync.aligned.m8n8.x2.shared.b16 {%0,%1}, [%2];"
                 : "=r"(r[0]), "=r"(r[1]) : "r"(a));
}
__device__ __forceinline__ void mma_bf16(float* d, const uint32_t* a, const uint32_t* b) {
    asm volatile("mma.sync.aligned.m16n8k16.row.col.f32.bf16.bf16.f32 "
                 "{%0,%1,%2,%3}, {%4,%5,%6,%7}, {%8,%9}, {%0,%1,%2,%3};"
                 : "+f"(d[0]), "+f"(d[1]), "+f"(d[2]), "+f"(d[3])
                 : "r"(a[0]), "r"(a[1]), "r"(a[2]), "r"(a[3]), "r"(b[0]), "r"(b[1]));
}

// ---------------- prep kernels ---------------------------------------------
__global__ void transpose_kernel(const float* __restrict__ in, float* __restrict__ out, int R, int C) {
    __shared__ float t[32][33];
    const int bx = blockIdx.x * 32, by = blockIdx.y * 32;
    const int x = threadIdx.x, y = threadIdx.y;
#pragma unroll
    for (int i = 0; i < 32; i += 8) t[y + i][x] = in[(size_t)(by + y + i) * C + bx + x];
    __syncthreads();
#pragma unroll
    for (int i = 0; i < 32; i += 8) out[(size_t)(bx + y + i) * R + by + x] = t[x][y + i];
}

// x [n] fp32 -> hi/lo bf16
__global__ void split_bf16_kernel(const float4* __restrict__ in,
                                  __nv_bfloat16* __restrict__ oh,
                                  __nv_bfloat16* __restrict__ ol, int n4) {
    const int i = blockIdx.x * blockDim.x + threadIdx.x;
    if (i >= n4) return;
    float4 v = in[i];
    __nv_bfloat16 h[4], l[4];
    const float vv[4] = {v.x, v.y, v.z, v.w};
#pragma unroll
    for (int k = 0; k < 4; k++) {
        h[k] = __float2bfloat16(vv[k]);
        l[k] = __float2bfloat16(vv[k] - __bfloat162float(h[k]));
    }
    *(uint2*)(oh + (size_t)i * 4) = *(const uint2*)h;
    *(uint2*)(ol + (size_t)i * 4) = *(const uint2*)l;
}

// W [R=256][C=1024] fp32 -> out hi/lo [C][R] bf16 (transposed)
__global__ void transpose_split_bf16_kernel(const float* __restrict__ in,
                                            __nv_bfloat16* __restrict__ oh,
                                            __nv_bfloat16* __restrict__ ol,
                                            int R, int C) {
    __shared__ float t[32][33];
    const int bx = blockIdx.x * 32, by = blockIdx.y * 32;
    const int x = threadIdx.x, y = threadIdx.y;
#pragma unroll
    for (int i = 0; i < 32; i += 8) t[y + i][x] = in[(size_t)(by + y + i) * C + bx + x];
    __syncthreads();
#pragma unroll
    for (int i = 0; i < 32; i += 8) {
        const float v = t[x][y + i];
        const __nv_bfloat16 h = __float2bfloat16(v);
        const __nv_bfloat16 l = __float2bfloat16(v - __bfloat162float(h));
        oh[(size_t)(bx + y + i) * R + by + x] = h;
        ol[(size_t)(bx + y + i) * R + by + x] = l;
    }
}

// ---------------- tropical kernel (SIMT, R7) --------------------------------
#define K1_ROW 200
#define K1_BUF (16 * K1_ROW)
#define WTO    132
__global__ __launch_bounds__(256, 3) void dtn_trop_kernel(const float* __restrict__ bt) {
    __shared__ float sm[8448];
    const int tid = threadIdx.x, tx = tid & 15, ty = tid >> 4;
    const int m0 = blockIdx.y * 128, n0 = blockIdx.x * 64;
    const uint32_t smb = (uint32_t)__cvta_generic_to_shared(sm);
    const int xrow = tid >> 5, xcol = tid & 31, wrow = tid >> 4, wcol = tid & 15;
    const float* xg  = g_xT  + (size_t)xrow * T_TOT + m0 + xcol * 4;
    const float* wtg = g_WtT + (size_t)wrow * FFN   + n0 + wcol * 4;

    const float NEG_INF = __int_as_float(0xff800000);
    float tmax[8][4];
#pragma unroll
    for (int i = 0; i < 8; i++)
#pragma unroll
        for (int j = 0; j < 4; j++) tmax[i][j] = NEG_INF;

    cp16(smb + (uint32_t)((xrow)     * K1_ROW + xcol * 4) * 4, xg);
    cp16(smb + (uint32_t)((xrow + 8) * K1_ROW + xcol * 4) * 4, xg + (size_t)8 * T_TOT);
    cp16(smb + (uint32_t)(wrow * K1_ROW + WTO + wcol * 4) * 4, wtg);
    cp_commit();

    for (int ch = 0; ch < 16; ch++) {
        const int p = ch & 1;
        if (ch < 15) {
            const uint32_t b = smb + (uint32_t)((1 - p) * K1_BUF) * 4;
            const size_t xo = (size_t)(ch + 1) * 16 * T_TOT, wo = (size_t)(ch + 1) * 16 * FFN;
            cp16(b + (uint32_t)((xrow)     * K1_ROW + xcol * 4) * 4, xg + xo);
            cp16(b + (uint32_t)((xrow + 8) * K1_ROW + xcol * 4) * 4, xg + xo + (size_t)8 * T_TOT);
            cp16(b + (uint32_t)(wrow * K1_ROW + WTO + wcol * 4) * 4, wtg + wo);
            cp_commit(); cp_wait<1>();
        } else cp_wait<0>();
        __syncthreads();
        const float* buf = sm + p * K1_BUF;
#pragma unroll
        for (int kk = 0; kk < 16; kk++) {
            const float* row = buf + kk * K1_ROW;
            const float4 xa0 = *(const float4*)(row + ty * 8);
            const float4 xa1 = *(const float4*)(row + ty * 8 + 4);
            const float4 wa  = *(const float4*)(row + WTO + tx * 4);
            const float xm[8] = {xa0.x, xa0.y, xa0.z, xa0.w, xa1.x, xa1.y, xa1.z, xa1.w};
            const unsigned long long wp[2] = {pack2(wa.x, wa.y), pack2(wa.z, wa.w)};
#pragma unroll
            for (int mi = 0; mi < 8; mi++) {
                const unsigned long long xd = pack2(xm[mi], xm[mi]);
#pragma unroll
                for (int pp = 0; pp < 2; pp++) {
                    float tlo, thi;
                    unpack2(add2(xd, wp[pp]), tlo, thi);
                    tmax[mi][2*pp+0] = fmaxf(tmax[mi][2*pp+0], tlo);
                    tmax[mi][2*pp+1] = fmaxf(tmax[mi][2*pp+1], thi);
                }
            }
        }
        __syncthreads();
    }
#pragma unroll
    for (int ni = 0; ni < 4; ni++) {
        const float btj = bt[n0 + tx * 4 + ni];
#pragma unroll
        for (int mi = 0; mi < 8; mi++)
            sm[(tx * 4 + ni) * 132 + ty * 8 + mi] = tmax[mi][ni] + btj;
    }
    __syncthreads();
#pragma unroll
    for (int r = 0; r < 8; r++) {
        const int idx = tid + r * 256, row = idx >> 5, c = idx & 31;
        *(float4*)(g_tT + (size_t)(n0 + row) * T_TOT + m0 + c * 4) =
            *(const float4*)(sm + row * 132 + c * 4);
    }
}

// ---------------- cg kernel: mma.sync bf16 split + epilogue ------------------
// tile 128 tok x 64 j; 8 warps: wm = w&3 (m group of 32), wj = w>>2 (j group of 32)
// smem rows: 80B stride (conflict-free ldmatrix). Per buffer (40960B):
//   AH 0, AL 10240 (128 rows x 32 bf16), B mats 64 rows: BCh 20480, BCl 25600,
//   BGh 30720, BGl 35840. Two buffers = 81920B dynamic smem.
#define CG_RS   80
#define CG_AH   0
#define CG_AL   10240
#define CG_BB   20480
#define CG_BSZ  5120
#define CG_BUF  40960
#define CG_SMEM 81920

__global__ __launch_bounds__(256, 1) void dtn_cg_kernel(
    const float* __restrict__ sl_cvx, const float* __restrict__ of_cvx,
    const float* __restrict__ sl_ccv, const float* __restrict__ of_ccv,
    const float* __restrict__ alpha,  const float* __restrict__ bc,
    const float* __restrict__ bg)
{
    extern __shared__ char dsm[];
    const int tid  = threadIdx.x;
    const int wid  = tid >> 5;
    const int lane = tid & 31;
    const int n0   = blockIdx.x * 64;
    const int m0   = blockIdx.y * 128;
    const int wm   = wid & 3;     // token group (32 rows)
    const int wj   = wid >> 2;    // j group (32 cols)
    const uint32_t smb = (uint32_t)__cvta_generic_to_shared(dsm);

    const __nv_bfloat16* bmat[4] = {g_Wch, g_Wcl, g_Wgh, g_Wgl};

    auto load_chunk = [&](int ch) {
        const int kc = ch * 32;
        const uint32_t bb = smb + (uint32_t)((ch & 1) * CG_BUF);
#pragma unroll
        for (int i = 0; i < 4; i++) {                 // A: hi then lo
            const int idx = tid + i * 256;            // 0..1023
            const int split = idx >> 9;               // 0=h 1=l
            const int rem = idx & 511, row = rem >> 2, seg = rem & 3;
            const __nv_bfloat16* src = (split ? g_xl : g_xh) +
                (size_t)(m0 + row) * DM + kc + seg * 8;
            cp16(bb + (split ? CG_AL : CG_AH) + row * CG_RS + seg * 16, src);
        }
#pragma unroll
        for (int i = 0; i < 4; i++) {                 // B: 4 mats
            const int idx = tid + i * 256;
            const int mat = idx >> 8;
            const int rem = idx & 255, row = rem >> 2, seg = rem & 3;
            cp16(bb + CG_BB + mat * CG_BSZ + row * CG_RS + seg * 16,
                 bmat[mat] + (size_t)(n0 + row) * DM + kc + seg * 8);
        }
    };

    float cacc[2][4][4], gacc[2][4][4];
#pragma unroll
    for (int mt = 0; mt < 2; mt++)
#pragma unroll
        for (int nt = 0; nt < 4; nt++)
#pragma unroll
            for (int v = 0; v < 4; v++) { cacc[mt][nt][v] = 0.0f; gacc[mt][nt][v] = 0.0f; }

    load_chunk(0); cp_commit();
    load_chunk(1); cp_commit();

    for (int ch = 0; ch < 8; ch++) {
        if (ch < 7) cp_wait<1>(); else cp_wait<0>();
        __syncthreads();
        const uint32_t bb = smb + (uint32_t)((ch & 1) * CG_BUF);

        // A fragments: [split][mt][kt][4]
        uint32_t af[2][2][2][4];
#pragma unroll
        for (int sp = 0; sp < 2; sp++)
#pragma unroll
            for (int mt = 0; mt < 2; mt++)
#pragma unroll
                for (int kt = 0; kt < 2; kt++) {
                    const uint32_t a = bb + (sp ? CG_AL : CG_AH) +
                        (uint32_t)(wm * 32 + mt * 16 + (lane & 15)) * CG_RS +
                        (uint32_t)(kt * 2 + (lane >> 4)) * 16;
                    ldsm4(af[sp][mt][kt], a);
                }
        // B fragments per mat: [nt][kt][2]
#pragma unroll
        for (int gm = 0; gm < 2; gm++) {             // 0: c (Wc), 1: g (Wg)
            uint32_t bh[4][2][2], bl[4][2][2];
#pragma unroll
            for (int nt = 0; nt < 4; nt++)
#pragma unroll
                for (int kt = 0; kt < 2; kt++) {
                    const uint32_t rowoff =
                        (uint32_t)(wj * 32 + nt * 8 + (lane & 7)) * CG_RS +
                        (uint32_t)(kt * 2 + ((lane >> 3) & 1)) * 16;
                    ldsm2(bh[nt][kt], bb + CG_BB + (gm * 2 + 0) * CG_BSZ + rowoff);
                    ldsm2(bl[nt][kt], bb + CG_BB + (gm * 2 + 1) * CG_BSZ + rowoff);
                }
            float (*acc)[4][4] = gm ? gacc : cacc;
#pragma unroll
            for (int mt = 0; mt < 2; mt++)
#pragma unroll
                for (int nt = 0; nt < 4; nt++)
#pragma unroll
                    for (int kt = 0; kt < 2; kt++) {
                        mma_bf16(acc[mt][nt], af[0][mt][kt], bh[nt][kt]);
                        mma_bf16(acc[mt][nt], af[0][mt][kt], bl[nt][kt]);
                        mma_bf16(acc[mt][nt], af[1][mt][kt], bh[nt][kt]);
                    }
        }
        __syncthreads();
        if (ch + 2 < 8) { load_chunk(ch + 2); cp_commit(); }
    }

    // ---- epilogue: fused = g*trop + (1-g)*gelu(c) --------------------------
    float* stage = (float*)dsm;   // [64 j][132] floats, reuse buffers
#pragma unroll
    for (int nt = 0; nt < 4; nt++) {
#pragma unroll
        for (int ci = 0; ci < 2; ci++) {
            const int jl = wj * 32 + nt * 8 + ((lane & 3) << 1) + ci;
            const int j  = n0 + jl;
            const float4 sc0 = *(const float4*)(sl_cvx + (size_t)j * 8);
            const float4 sc1 = *(const float4*)(sl_cvx + (size_t)j * 8 + 4);
            const float4 oc0 = *(const float4*)(of_cvx + (size_t)j * 8);
            const float4 oc1 = *(const float4*)(of_cvx + (size_t)j * 8 + 4);
            const float4 sv0 = *(const float4*)(sl_ccv + (size_t)j * 8);
            const float4 sv1 = *(const float4*)(sl_ccv + (size_t)j * 8 + 4);
            const float4 ov0 = *(const float4*)(of_ccv + (size_t)j * 8);
            const float4 ov1 = *(const float4*)(of_ccv + (size_t)j * 8 + 4);
            const float s   = sigf(alpha[j]);
            const float bcj = bc[j];
            const float bgj = bg[j];
#pragma unroll
            for (int mt = 0; mt < 2; mt++)
#pragma unroll
                for (int rh = 0; rh < 2; rh++) {
                    const int tok = wm * 32 + mt * 16 + (lane >> 2) + rh * 8;
                    const float t = g_tT[(size_t)j * T_TOT + m0 + tok];
                    float cvx = fmaf(t, sc0.x, oc0.x);
                    cvx = fmaxf(cvx, fmaf(t, sc0.y, oc0.y));
                    cvx = fmaxf(cvx, fmaf(t, sc0.z, oc0.z));
                    cvx = fmaxf(cvx, fmaf(t, sc0.w, oc0.w));
                    cvx = fmaxf(cvx, fmaf(t, sc1.x, oc1.x));
                    cvx = fmaxf(cvx, fmaf(t, sc1.y, oc1.y));
                    cvx = fmaxf(cvx, fmaf(t, sc1.z, oc1.z));
                    cvx = fmaxf(cvx, fmaf(t, sc1.w, oc1.w));
                    float ccv = fmaf(t, sv0.x, ov0.x);
                    ccv = fminf(ccv, fmaf(t, sv0.y, ov0.y));
                    ccv = fminf(ccv, fmaf(t, sv0.z, ov0.z));
                    ccv = fminf(ccv, fmaf(t, sv0.w, ov0.w));
                    ccv = fminf(ccv, fmaf(t, sv1.x, ov1.x));
                    ccv = fminf(ccv, fmaf(t, sv1.y, ov1.y));
                    ccv = fminf(ccv, fmaf(t, sv1.z, ov1.z));
                    ccv = fminf(ccv, fmaf(t, sv1.w, ov1.w));
                    const float trop = s * cvx + (1.0f - s) * ccv;

                    const float cv  = cacc[mt][nt][rh * 2 + ci] + bcj;
                    const float cls = 0.5f * cv * (1.0f + erff(cv * 0.70710678118654752f));
                    const float gv  = sigf(gacc[mt][nt][rh * 2 + ci] + bgj);
                    stage[jl * 132 + tok] = gv * trop + (1.0f - gv) * cls;
                }
        }
    }
    __syncthreads();
#pragma unroll
    for (int r = 0; r < 8; r++) {
        const int idx = tid + r * 256, row = idx >> 5, c = idx & 31;
        *(float4*)(g_fusedT + (size_t)(n0 + row) * T_TOT + m0 + c * 4) =
            *(const float4*)(stage + row * 132 + c * 4);
    }
}

// ---------------- out kernel (FFMA2, round-5) -------------------------------
#define K2_ROW 264
#define K2_BUF (16 * K2_ROW)
#define WDO    132
__global__ __launch_bounds__(256, 2) void dtn_out_kernel(
    const float* __restrict__ Wd, const float* __restrict__ bd, float* __restrict__ out)
{
    __shared__ float sm[2 * K2_BUF];
    const int tid = threadIdx.x, tx = tid & 15, ty = tid >> 4;
    const int m0 = blockIdx.y * 128, n0 = blockIdx.x * 128;
    const uint32_t smb = (uint32_t)__cvta_generic_to_shared(sm);
    const int lrow = tid >> 5, lcol = tid & 31;
    const float* fg = g_fusedT + (size_t)lrow * T_TOT + m0 + lcol * 4;
    const float* wg = Wd       + (size_t)lrow * DM   + n0 + lcol * 4;

    unsigned long long a2[4][8];
#pragma unroll
    for (int i = 0; i < 4; i++)
#pragma unroll
        for (int j = 0; j < 8; j++) a2[i][j] = 0ull;

    cp16(smb + (uint32_t)((lrow)     * K2_ROW + lcol * 4) * 4, fg);
    cp16(smb + (uint32_t)((lrow + 8) * K2_ROW + lcol * 4) * 4, fg + (size_t)8 * T_TOT);
    cp16(smb + (uint32_t)((lrow)     * K2_ROW + WDO + lcol * 4) * 4, wg);
    cp16(smb + (uint32_t)((lrow + 8) * K2_ROW + WDO + lcol * 4) * 4, wg + (size_t)8 * DM);
    cp_commit();

    for (int ch = 0; ch < 64; ch++) {
        const int p = ch & 1;
        if (ch < 63) {
            const uint32_t b = smb + (uint32_t)((1 - p) * K2_BUF) * 4;
            const size_t fo = (size_t)(ch + 1) * 16 * T_TOT, wo = (size_t)(ch + 1) * 16 * DM;
            cp16(b + (uint32_t)((lrow)     * K2_ROW + lcol * 4) * 4, fg + fo);
            cp16(b + (uint32_t)((lrow + 8) * K2_ROW + lcol * 4) * 4, fg + fo + (size_t)8 * T_TOT);
            cp16(b + (uint32_t)((lrow)     * K2_ROW + WDO + lcol * 4) * 4, wg + wo);
            cp16(b + (uint32_t)((lrow + 8) * K2_ROW + WDO + lcol * 4) * 4, wg + wo + (size_t)8 * DM);
            cp_commit(); cp_wait<1>();
        } else cp_wait<0>();
        __syncthreads();
        const float* buf = sm + p * K2_BUF;
#pragma unroll
        for (int kk = 0; kk < 16; kk++) {
            const float* row = buf + kk * K2_ROW;
            const float4 fa0 = *(const float4*)(row + ty * 8);
            const float4 fa1 = *(const float4*)(row + ty * 8 + 4);
            const float4 wa0 = *(const float4*)(row + WDO + tx * 4);
            const float4 wa1 = *(const float4*)(row + WDO + 64 + tx * 4);
            const unsigned long long xp[4] = {
                pack2(fa0.x, fa0.y), pack2(fa0.z, fa0.w),
                pack2(fa1.x, fa1.y), pack2(fa1.z, fa1.w)};
            const float wn[8] = {wa0.x, wa0.y, wa0.z, wa0.w, wa1.x, wa1.y, wa1.z, wa1.w};
#pragma unroll
            for (int ni = 0; ni < 8; ni++) {
                const unsigned long long wd2 = pack2(wn[ni], wn[ni]);
#pragma unroll
                for (int mp = 0; mp < 4; mp++) a2[mp][ni] = fma2(xp[mp], wd2, a2[mp][ni]);
            }
        }
        __syncthreads();
    }
    const float4 bdv0 = *(const float4*)(bd + n0 + tx * 4);
    const float4 bdv1 = *(const float4*)(bd + n0 + 64 + tx * 4);
#pragma unroll
    for (int mp = 0; mp < 4; mp++) {
        float lo[8], hi[8];
#pragma unroll
        for (int ni = 0; ni < 8; ni++) unpack2(a2[mp][ni], lo[ni], hi[ni]);
        float4 o;
        const size_t r0 = (size_t)(m0 + ty * 8 + mp * 2 + 0) * DM;
        const size_t r1 = (size_t)(m0 + ty * 8 + mp * 2 + 1) * DM;
        o.x = lo[0] + bdv0.x; o.y = lo[1] + bdv0.y; o.z = lo[2] + bdv0.z; o.w = lo[3] + bdv0.w;
        *(float4*)(out + r0 + n0 + tx * 4) = o;
        o.x = lo[4] + bdv1.x; o.y = lo[5] + bdv1.y; o.z = lo[6] + bdv1.z; o.w = lo[7] + bdv1.w;
        *(float4*)(out + r0 + n0 + 64 + tx * 4) = o;
        o.x = hi[0] + bdv0.x; o.y = hi[1] + bdv0.y; o.z = hi[2] + bdv0.z; o.w = hi[3] + bdv0.w;
        *(float4*)(out + r1 + n0 + tx * 4) = o;
        o.x = hi[4] + bdv1.x; o.y = hi[5] + bdv1.y; o.z = hi[6] + bdv1.z; o.w = hi[7] + bdv1.w;
        *(float4*)(out + r1 + n0 + 64 + tx * 4) = o;
    }
}

extern "C" void kernel_launch(void* const* d_in, const int* in_sizes, int n_in,
                              void* d_out, int out_size) {
    const float* x      = (const float*)d_in[0];
    const float* Wt     = (const float*)d_in[1];
    const float* bt     = (const float*)d_in[2];
    const float* sl_cvx = (const float*)d_in[3];
    const float* of_cvx = (const float*)d_in[4];
    const float* sl_ccv = (const float*)d_in[5];
    const float* of_ccv = (const float*)d_in[6];
    const float* alpha  = (const float*)d_in[7];
    const float* Wc     = (const float*)d_in[8];
    const float* bc     = (const float*)d_in[9];
    const float* Wg     = (const float*)d_in[10];
    const float* bg     = (const float*)d_in[11];
    const float* Wd     = (const float*)d_in[12];
    const float* bd     = (const float*)d_in[13];
    float* out = (float*)d_out;

    float *xT, *wtT;
    __nv_bfloat16 *xh, *xl, *wch, *wcl, *wgh, *wgl;
    cudaGetSymbolAddress((void**)&xT,  g_xT);
    cudaGetSymbolAddress((void**)&wtT, g_WtT);
    cudaGetSymbolAddress((void**)&xh,  g_xh);
    cudaGetSymbolAddress((void**)&xl,  g_xl);
    cudaGetSymbolAddress((void**)&wch, g_Wch);
    cudaGetSymbolAddress((void**)&wcl, g_Wcl);
    cudaGetSymbolAddress((void**)&wgh, g_Wgh);
    cudaGetSymbolAddress((void**)&wgl, g_Wgl);

    static int smem_set = 0;
    if (!smem_set) {
        cudaFuncSetAttribute(dtn_cg_kernel, cudaFuncAttributeMaxDynamicSharedMemorySize, CG_SMEM);
        smem_set = 1;
    }

    transpose_kernel<<<dim3(DM / 32, T_TOT / 32), dim3(32, 8)>>>(x, xT, T_TOT, DM);
    transpose_kernel<<<dim3(DM / 32, FFN / 32), dim3(32, 8)>>>(Wt, wtT, FFN, DM);
    split_bf16_kernel<<<(T_TOT * DM / 4 + 255) / 256, 256>>>((const float4*)x, xh, xl, T_TOT * DM / 4);
    transpose_split_bf16_kernel<<<dim3(FFN / 32, DM / 32), dim3(32, 8)>>>(Wc, wch, wcl, DM, FFN);
    transpose_split_bf16_kernel<<<dim3(FFN / 32, DM / 32), dim3(32, 8)>>>(Wg, wgh, wgl, DM, FFN);

    dtn_trop_kernel<<<dim3(FFN / 64, T_TOT / 128), 256>>>(bt);
    dtn_cg_kernel<<<dim3(FFN / 64, T_TOT / 128), 256, CG_SMEM>>>(
        sl_cvx, of_cvx, sl_ccv, of_ccv, alpha, bc, bg);
    dtn_out_kernel<<<dim3(DM / 128, T_TOT / 128), 256>>>(Wd, bd, out);
}

// round 10
// speedup vs baseline: 1.4495x; 1.2697x over previous
#include <cuda_runtime.h>
#include <cuda_bf16.h>
#include <math.h>
#include <stdint.h>

#define T_TOT 32768
#define DM    256
#define FFN   1024

// ---------------- scratch (allocation-free rule) ---------------------------
__device__ float g_xT  [(size_t)DM * T_TOT];      // x^T [256][32768] fp32
__device__ float g_WtT [(size_t)DM * FFN];        // Wt^T [256][1024] fp32
__device__ float g_tT  [(size_t)FFN * T_TOT];     // tropical+bt [1024][32768]
__device__ __nv_bfloat16 g_xh [(size_t)T_TOT * DM];  // x hi [32768][256]
__device__ __nv_bfloat16 g_xl [(size_t)T_TOT * DM];
__device__ __nv_bfloat16 g_Wch[(size_t)FFN * DM];    // Wc^T hi [1024][256]
__device__ __nv_bfloat16 g_Wcl[(size_t)FFN * DM];
__device__ __nv_bfloat16 g_Wgh[(size_t)FFN * DM];
__device__ __nv_bfloat16 g_Wgl[(size_t)FFN * DM];
__device__ __nv_bfloat16 g_fh [(size_t)T_TOT * FFN]; // fused hi [32768][1024]
__device__ __nv_bfloat16 g_fl [(size_t)T_TOT * FFN]; // fused lo
__device__ __nv_bfloat16 g_Wdh[(size_t)DM * FFN];    // Wd^T hi [256][1024]
__device__ __nv_bfloat16 g_Wdl[(size_t)DM * FFN];

__device__ __forceinline__ float sigf(float z) { return 1.0f / (1.0f + __expf(-z)); }
__device__ __forceinline__ void cp16(uint32_t s, const void* g) {
    asm volatile("cp.async.cg.shared.global [%0], [%1], 16;" :: "r"(s), "l"(g));
}
__device__ __forceinline__ void cp_commit() { asm volatile("cp.async.commit_group;" ::: "memory"); }
template <int N> __device__ __forceinline__ void cp_wait() {
    asm volatile("cp.async.wait_group %0;" :: "n"(N) : "memory");
}
__device__ __forceinline__ void ldsm4(uint32_t* r, uint32_t a) {
    asm volatile("ldmatrix.sync.aligned.m8n8.x4.shared.b16 {%0,%1,%2,%3}, [%4];"
                 : "=r"(r[0]), "=r"(r[1]), "=r"(r[2]), "=r"(r[3]) : "r"(a));
}
__device__ __forceinline__ void ldsm2(uint32_t* r, uint32_t a) {
    asm volatile("ldmatrix.sync.aligned.m8n8.x2.shared.b16 {%0,%1}, [%2];"
                 : "=r"(r[0]), "=r"(r[1]) : "r"(a));
}
__device__ __forceinline__ void mma_bf16(float* d, const uint32_t* a, const uint32_t* b) {
    asm volatile("mma.sync.aligned.m16n8k16.row.col.f32.bf16.bf16.f32 "
                 "{%0,%1,%2,%3}, {%4,%5,%6,%7}, {%8,%9}, {%0,%1,%2,%3};"
                 : "+f"(d[0]), "+f"(d[1]), "+f"(d[2]), "+f"(d[3])
                 : "r"(a[0]), "r"(a[1]), "r"(a[2]), "r"(a[3]), "r"(b[0]), "r"(b[1]));
}

// ---------------- prep kernels ---------------------------------------------
__global__ void transpose_kernel(const float* __restrict__ in, float* __restrict__ out, int R, int C) {
    __shared__ float t[32][33];
    const int bx = blockIdx.x * 32, by = blockIdx.y * 32;
    const int x = threadIdx.x, y = threadIdx.y;
#pragma unroll
    for (int i = 0; i < 32; i += 8) t[y + i][x] = in[(size_t)(by + y + i) * C + bx + x];
    __syncthreads();
#pragma unroll
    for (int i = 0; i < 32; i += 8) out[(size_t)(bx + y + i) * R + by + x] = t[x][y + i];
}
__global__ void split_bf16_kernel(const float4* __restrict__ in,
                                  __nv_bfloat16* __restrict__ oh,
                                  __nv_bfloat16* __restrict__ ol, int n4) {
    const int i = blockIdx.x * blockDim.x + threadIdx.x;
    if (i >= n4) return;
    float4 v = in[i];
    __nv_bfloat16 h[4], l[4];
    const float vv[4] = {v.x, v.y, v.z, v.w};
#pragma unroll
    for (int k = 0; k < 4; k++) {
        h[k] = __float2bfloat16(vv[k]);
        l[k] = __float2bfloat16(vv[k] - __bfloat162float(h[k]));
    }
    *(uint2*)(oh + (size_t)i * 4) = *(const uint2*)h;
    *(uint2*)(ol + (size_t)i * 4) = *(const uint2*)l;
}
// in[R][C] fp32 -> out hi/lo [C][R] bf16
__global__ void transpose_split_bf16_kernel(const float* __restrict__ in,
                                            __nv_bfloat16* __restrict__ oh,
                                            __nv_bfloat16* __restrict__ ol,
                                            int R, int C) {
    __shared__ float t[32][33];
    const int bx = blockIdx.x * 32, by = blockIdx.y * 32;
    const int x = threadIdx.x, y = threadIdx.y;
#pragma unroll
    for (int i = 0; i < 32; i += 8) t[y + i][x] = in[(size_t)(by + y + i) * C + bx + x];
    __syncthreads();
#pragma unroll
    for (int i = 0; i < 32; i += 8) {
        const float v = t[x][y + i];
        const __nv_bfloat16 h = __float2bfloat16(v);
        const __nv_bfloat16 l = __float2bfloat16(v - __bfloat162float(h));
        oh[(size_t)(bx + y + i) * R + by + x] = h;
        ol[(size_t)(bx + y + i) * R + by + x] = l;
    }
}

// ---------------- tropical kernel (SIMT, scalar FADD+FMNMX) ------------------
#define K1_ROW 200
#define K1_BUF (16 * K1_ROW)
#define WTO    132
__global__ __launch_bounds__(256, 3) void dtn_trop_kernel(const float* __restrict__ bt) {
    __shared__ float sm[8448];
    const int tid = threadIdx.x, tx = tid & 15, ty = tid >> 4;
    const int m0 = blockIdx.y * 128, n0 = blockIdx.x * 64;
    const uint32_t smb = (uint32_t)__cvta_generic_to_shared(sm);
    const int xrow = tid >> 5, xcol = tid & 31, wrow = tid >> 4, wcol = tid & 15;
    const float* xg  = g_xT  + (size_t)xrow * T_TOT + m0 + xcol * 4;
    const float* wtg = g_WtT + (size_t)wrow * FFN   + n0 + wcol * 4;

    const float NEG_INF = __int_as_float(0xff800000);
    float tmax[8][4];
#pragma unroll
    for (int i = 0; i < 8; i++)
#pragma unroll
        for (int j = 0; j < 4; j++) tmax[i][j] = NEG_INF;

    cp16(smb + (uint32_t)((xrow)     * K1_ROW + xcol * 4) * 4, xg);
    cp16(smb + (uint32_t)((xrow + 8) * K1_ROW + xcol * 4) * 4, xg + (size_t)8 * T_TOT);
    cp16(smb + (uint32_t)(wrow * K1_ROW + WTO + wcol * 4) * 4, wtg);
    cp_commit();

    for (int ch = 0; ch < 16; ch++) {
        const int p = ch & 1;
        if (ch < 15) {
            const uint32_t b = smb + (uint32_t)((1 - p) * K1_BUF) * 4;
            const size_t xo = (size_t)(ch + 1) * 16 * T_TOT, wo = (size_t)(ch + 1) * 16 * FFN;
            cp16(b + (uint32_t)((xrow)     * K1_ROW + xcol * 4) * 4, xg + xo);
            cp16(b + (uint32_t)((xrow + 8) * K1_ROW + xcol * 4) * 4, xg + xo + (size_t)8 * T_TOT);
            cp16(b + (uint32_t)(wrow * K1_ROW + WTO + wcol * 4) * 4, wtg + wo);
            cp_commit(); cp_wait<1>();
        } else cp_wait<0>();
        __syncthreads();
        const float* buf = sm + p * K1_BUF;
#pragma unroll
        for (int kk = 0; kk < 16; kk++) {
            const float* row = buf + kk * K1_ROW;
            const float4 xa0 = *(const float4*)(row + ty * 8);
            const float4 xa1 = *(const float4*)(row + ty * 8 + 4);
            const float4 wa  = *(const float4*)(row + WTO + tx * 4);
            const float xm[8] = {xa0.x, xa0.y, xa0.z, xa0.w, xa1.x, xa1.y, xa1.z, xa1.w};
            const float wn[4] = {wa.x, wa.y, wa.z, wa.w};
#pragma unroll
            for (int mi = 0; mi < 8; mi++)
#pragma unroll
                for (int ni = 0; ni < 4; ni++)
                    tmax[mi][ni] = fmaxf(tmax[mi][ni], xm[mi] + wn[ni]);
        }
        __syncthreads();
    }
#pragma unroll
    for (int ni = 0; ni < 4; ni++) {
        const float btj = bt[n0 + tx * 4 + ni];
#pragma unroll
        for (int mi = 0; mi < 8; mi++)
            sm[(tx * 4 + ni) * 132 + ty * 8 + mi] = tmax[mi][ni] + btj;
    }
    __syncthreads();
#pragma unroll
    for (int r = 0; r < 8; r++) {
        const int idx = tid + r * 256, row = idx >> 5, c = idx & 31;
        *(float4*)(g_tT + (size_t)(n0 + row) * T_TOT + m0 + c * 4) =
            *(const float4*)(sm + row * 132 + c * 4);
    }
}

// ---------------- cg kernel: mma.sync bf16 split + epilogue ------------------
// tile 128 tok x 64 j; 8 warps; 2 CTAs/SM.
#define CG_RS   80
#define CG_AH   0
#define CG_AL   10240
#define CG_BB   20480
#define CG_BSZ  5120
#define CG_BUF  40960
#define CG_SMEM 81920

__global__ __launch_bounds__(256, 2) void dtn_cg_kernel(
    const float* __restrict__ sl_cvx, const float* __restrict__ of_cvx,
    const float* __restrict__ sl_ccv, const float* __restrict__ of_ccv,
    const float* __restrict__ alpha,  const float* __restrict__ bc,
    const float* __restrict__ bg)
{
    extern __shared__ char dsm[];
    const int tid  = threadIdx.x;
    const int wid  = tid >> 5;
    const int lane = tid & 31;
    const int n0   = blockIdx.x * 64;
    const int m0   = blockIdx.y * 128;
    const int wm   = wid & 3;
    const int wj   = wid >> 2;
    const uint32_t smb = (uint32_t)__cvta_generic_to_shared(dsm);

    const __nv_bfloat16* bmat[4] = {g_Wch, g_Wcl, g_Wgh, g_Wgl};

    auto load_chunk = [&](int ch) {
        const int kc = ch * 32;
        const uint32_t bb = smb + (uint32_t)((ch & 1) * CG_BUF);
#pragma unroll
        for (int i = 0; i < 4; i++) {
            const int idx = tid + i * 256;
            const int split = idx >> 9;
            const int rem = idx & 511, row = rem >> 2, seg = rem & 3;
            const __nv_bfloat16* src = (split ? g_xl : g_xh) +
                (size_t)(m0 + row) * DM + kc + seg * 8;
            cp16(bb + (split ? CG_AL : CG_AH) + row * CG_RS + seg * 16, src);
        }
#pragma unroll
        for (int i = 0; i < 4; i++) {
            const int idx = tid + i * 256;
            const int mat = idx >> 8;
            const int rem = idx & 255, row = rem >> 2, seg = rem & 3;
            cp16(bb + CG_BB + mat * CG_BSZ + row * CG_RS + seg * 16,
                 bmat[mat] + (size_t)(n0 + row) * DM + kc + seg * 8);
        }
    };

    float cacc[2][4][4], gacc[2][4][4];
#pragma unroll
    for (int mt = 0; mt < 2; mt++)
#pragma unroll
        for (int nt = 0; nt < 4; nt++)
#pragma unroll
            for (int v = 0; v < 4; v++) { cacc[mt][nt][v] = 0.0f; gacc[mt][nt][v] = 0.0f; }

    load_chunk(0); cp_commit();
    load_chunk(1); cp_commit();

    for (int ch = 0; ch < 8; ch++) {
        if (ch < 7) cp_wait<1>(); else cp_wait<0>();
        __syncthreads();
        const uint32_t bb = smb + (uint32_t)((ch & 1) * CG_BUF);

        uint32_t af[2][2][2][4];
#pragma unroll
        for (int sp = 0; sp < 2; sp++)
#pragma unroll
            for (int mt = 0; mt < 2; mt++)
#pragma unroll
                for (int kt = 0; kt < 2; kt++) {
                    const uint32_t a = bb + (sp ? CG_AL : CG_AH) +
                        (uint32_t)(wm * 32 + mt * 16 + (lane & 15)) * CG_RS +
                        (uint32_t)(kt * 2 + (lane >> 4)) * 16;
                    ldsm4(af[sp][mt][kt], a);
                }
#pragma unroll
        for (int gm = 0; gm < 2; gm++) {
            float (*acc)[4][4] = gm ? gacc : cacc;
#pragma unroll
            for (int nt = 0; nt < 4; nt++) {
                uint32_t bh[2][2], bl[2][2];
#pragma unroll
                for (int kt = 0; kt < 2; kt++) {
                    const uint32_t rowoff =
                        (uint32_t)(wj * 32 + nt * 8 + (lane & 7)) * CG_RS +
                        (uint32_t)(kt * 2 + ((lane >> 3) & 1)) * 16;
                    ldsm2(bh[kt], bb + CG_BB + (gm * 2 + 0) * CG_BSZ + rowoff);
                    ldsm2(bl[kt], bb + CG_BB + (gm * 2 + 1) * CG_BSZ + rowoff);
                }
#pragma unroll
                for (int mt = 0; mt < 2; mt++)
#pragma unroll
                    for (int kt = 0; kt < 2; kt++) {
                        mma_bf16(acc[mt][nt], af[0][mt][kt], bh[kt]);
                        mma_bf16(acc[mt][nt], af[0][mt][kt], bl[kt]);
                        mma_bf16(acc[mt][nt], af[1][mt][kt], bh[kt]);
                    }
            }
        }
        __syncthreads();
        if (ch + 2 < 8) { load_chunk(ch + 2); cp_commit(); }
    }

    // ---- epilogue: fused -> bf16 hi/lo, token-major -----------------------
    __nv_bfloat16* sth = (__nv_bfloat16*)dsm;          // [128][72]
    __nv_bfloat16* stl = sth + 128 * 72;
#pragma unroll
    for (int nt = 0; nt < 4; nt++) {
#pragma unroll
        for (int ci = 0; ci < 2; ci++) {
            const int jl = wj * 32 + nt * 8 + ((lane & 3) << 1) + ci;
            const int j  = n0 + jl;
            const float4 sc0 = *(const float4*)(sl_cvx + (size_t)j * 8);
            const float4 sc1 = *(const float4*)(sl_cvx + (size_t)j * 8 + 4);
            const float4 oc0 = *(const float4*)(of_cvx + (size_t)j * 8);
            const float4 oc1 = *(const float4*)(of_cvx + (size_t)j * 8 + 4);
            const float4 sv0 = *(const float4*)(sl_ccv + (size_t)j * 8);
            const float4 sv1 = *(const float4*)(sl_ccv + (size_t)j * 8 + 4);
            const float4 ov0 = *(const float4*)(of_ccv + (size_t)j * 8);
            const float4 ov1 = *(const float4*)(of_ccv + (size_t)j * 8 + 4);
            const float s   = sigf(alpha[j]);
            const float bcj = bc[j];
            const float bgj = bg[j];
#pragma unroll
            for (int mt = 0; mt < 2; mt++)
#pragma unroll
                for (int rh = 0; rh < 2; rh++) {
                    const int tok = wm * 32 + mt * 16 + (lane >> 2) + rh * 8;
                    const float t = g_tT[(size_t)j * T_TOT + m0 + tok];
                    float cvx = fmaf(t, sc0.x, oc0.x);
                    cvx = fmaxf(cvx, fmaf(t, sc0.y, oc0.y));
                    cvx = fmaxf(cvx, fmaf(t, sc0.z, oc0.z));
                    cvx = fmaxf(cvx, fmaf(t, sc0.w, oc0.w));
                    cvx = fmaxf(cvx, fmaf(t, sc1.x, oc1.x));
                    cvx = fmaxf(cvx, fmaf(t, sc1.y, oc1.y));
                    cvx = fmaxf(cvx, fmaf(t, sc1.z, oc1.z));
                    cvx = fmaxf(cvx, fmaf(t, sc1.w, oc1.w));
                    float ccv = fmaf(t, sv0.x, ov0.x);
                    ccv = fminf(ccv, fmaf(t, sv0.y, ov0.y));
                    ccv = fminf(ccv, fmaf(t, sv0.z, ov0.z));
                    ccv = fminf(ccv, fmaf(t, sv0.w, ov0.w));
                    ccv = fminf(ccv, fmaf(t, sv1.x, ov1.x));
                    ccv = fminf(ccv, fmaf(t, sv1.y, ov1.y));
                    ccv = fminf(ccv, fmaf(t, sv1.z, ov1.z));
                    ccv = fminf(ccv, fmaf(t, sv1.w, ov1.w));
                    const float trop = s * cvx + (1.0f - s) * ccv;
                    const float cv  = cacc[mt][nt][rh * 2 + ci] + bcj;
                    const float cls = 0.5f * cv * (1.0f + erff(cv * 0.70710678118654752f));
                    const float gv  = sigf(gacc[mt][nt][rh * 2 + ci] + bgj);
                    const float fv  = gv * trop + (1.0f - gv) * cls;
                    const __nv_bfloat16 fh = __float2bfloat16(fv);
                    sth[tok * 72 + jl] = fh;
                    stl[tok * 72 + jl] = __float2bfloat16(fv - __bfloat162float(fh));
                }
        }
    }
    __syncthreads();
#pragma unroll
    for (int r = 0; r < 4; r++) {
        const int idx = tid + r * 256, row = idx >> 3, seg = idx & 7;
        *(uint4*)(g_fh + (size_t)(m0 + row) * FFN + n0 + seg * 8) =
            *(const uint4*)(sth + row * 72 + seg * 8);
        *(uint4*)(g_fl + (size_t)(m0 + row) * FFN + n0 + seg * 8) =
            *(const uint4*)(stl + row * 72 + seg * 8);
    }
}

// ---------------- out kernel: mma.sync bf16 split ---------------------------
// out[T,256] = fused @ Wd + bd. tile 128 tok x 64 n, K=1024, 8 warps, 2 CTA/SM.
#define OD_RS   80
#define OD_AH   0
#define OD_AL   10240
#define OD_BH   20480
#define OD_BL   25600
#define OD_BUF  30720
#define OD_SMEM 61440

__global__ __launch_bounds__(256, 2) void dtn_out_kernel(
    const float* __restrict__ bd, float* __restrict__ out)
{
    extern __shared__ char dsm[];
    const int tid  = threadIdx.x;
    const int wid  = tid >> 5;
    const int lane = tid & 31;
    const int n0   = blockIdx.x * 64;
    const int m0   = blockIdx.y * 128;
    const int wm   = wid & 3;
    const int wj   = wid >> 2;
    const uint32_t smb = (uint32_t)__cvta_generic_to_shared(dsm);

    auto load_chunk = [&](int ch) {
        const int kc = ch * 32;
        const uint32_t bb = smb + (uint32_t)((ch & 1) * OD_BUF);
#pragma unroll
        for (int i = 0; i < 4; i++) {
            const int idx = tid + i * 256;
            const int split = idx >> 9;
            const int rem = idx & 511, row = rem >> 2, seg = rem & 3;
            const __nv_bfloat16* src = (split ? g_fl : g_fh) +
                (size_t)(m0 + row) * FFN + kc + seg * 8;
            cp16(bb + (split ? OD_AL : OD_AH) + row * OD_RS + seg * 16, src);
        }
#pragma unroll
        for (int i = 0; i < 2; i++) {
            const int idx = tid + i * 256;
            const int split = idx >> 8;
            const int rem = idx & 255, row = rem >> 2, seg = rem & 3;
            cp16(bb + (split ? OD_BL : OD_BH) + row * OD_RS + seg * 16,
                 (split ? g_Wdl : g_Wdh) + (size_t)(n0 + row) * FFN + kc + seg * 8);
        }
    };

    float acc[2][4][4];
#pragma unroll
    for (int mt = 0; mt < 2; mt++)
#pragma unroll
        for (int nt = 0; nt < 4; nt++)
#pragma unroll
            for (int v = 0; v < 4; v++) acc[mt][nt][v] = 0.0f;

    load_chunk(0); cp_commit();
    load_chunk(1); cp_commit();

    for (int ch = 0; ch < 32; ch++) {
        if (ch < 31) cp_wait<1>(); else cp_wait<0>();
        __syncthreads();
        const uint32_t bb = smb + (uint32_t)((ch & 1) * OD_BUF);

        uint32_t af[2][2][2][4];
#pragma unroll
        for (int sp = 0; sp < 2; sp++)
#pragma unroll
            for (int mt = 0; mt < 2; mt++)
#pragma unroll
                for (int kt = 0; kt < 2; kt++) {
                    const uint32_t a = bb + (sp ? OD_AL : OD_AH) +
                        (uint32_t)(wm * 32 + mt * 16 + (lane & 15)) * OD_RS +
                        (uint32_t)(kt * 2 + (lane >> 4)) * 16;
                    ldsm4(af[sp][mt][kt], a);
                }
#pragma unroll
        for (int nt = 0; nt < 4; nt++) {
            uint32_t bh[2][2], bl[2][2];
#pragma unroll
            for (int kt = 0; kt < 2; kt++) {
                const uint32_t rowoff =
                    (uint32_t)(wj * 32 + nt * 8 + (lane & 7)) * OD_RS +
                    (uint32_t)(kt * 2 + ((lane >> 3) & 1)) * 16;
                ldsm2(bh[kt], bb + OD_BH + rowoff);
                ldsm2(bl[kt], bb + OD_BL + rowoff);
            }
#pragma unroll
            for (int mt = 0; mt < 2; mt++)
#pragma unroll
                for (int kt = 0; kt < 2; kt++) {
                    mma_bf16(acc[mt][nt], af[0][mt][kt], bh[kt]);
                    mma_bf16(acc[mt][nt], af[0][mt][kt], bl[kt]);
                    mma_bf16(acc[mt][nt], af[1][mt][kt], bh[kt]);
                }
        }
        __syncthreads();
        if (ch + 2 < 32) { load_chunk(ch + 2); cp_commit(); }
    }

    // ---- epilogue ----
    float* stage = (float*)dsm;   // [128][68]
#pragma unroll
    for (int nt = 0; nt < 4; nt++)
#pragma unroll
        for (int ci = 0; ci < 2; ci++) {
            const int col = wj * 32 + nt * 8 + ((lane & 3) << 1) + ci;
            const float bdv = bd[n0 + col];
#pragma unroll
            for (int mt = 0; mt < 2; mt++)
#pragma unroll
                for (int rh = 0; rh < 2; rh++) {
                    const int tok = wm * 32 + mt * 16 + (lane >> 2) + rh * 8;
                    stage[tok * 68 + col] = acc[mt][nt][rh * 2 + ci] + bdv;
                }
        }
    __syncthreads();
#pragma unroll
    for (int r = 0; r < 8; r++) {
        const int idx = tid + r * 256, row = idx >> 4, seg = idx & 15;
        *(float4*)(out + (size_t)(m0 + row) * DM + n0 + seg * 4) =
            *(const float4*)(stage + row * 68 + seg * 4);
    }
}

extern "C" void kernel_launch(void* const* d_in, const int* in_sizes, int n_in,
                              void* d_out, int out_size) {
    const float* x      = (const float*)d_in[0];
    const float* Wt     = (const float*)d_in[1];
    const float* bt     = (const float*)d_in[2];
    const float* sl_cvx = (const float*)d_in[3];
    const float* of_cvx = (const float*)d_in[4];
    const float* sl_ccv = (const float*)d_in[5];
    const float* of_ccv = (const float*)d_in[6];
    const float* alpha  = (const float*)d_in[7];
    const float* Wc     = (const float*)d_in[8];
    const float* bc     = (const float*)d_in[9];
    const float* Wg     = (const float*)d_in[10];
    const float* bg     = (const float*)d_in[11];
    const float* Wd     = (const float*)d_in[12];
    const float* bd     = (const float*)d_in[13];
    float* out = (float*)d_out;

    float *xT, *wtT;
    __nv_bfloat16 *xh, *xl, *wch, *wcl, *wgh, *wgl, *wdh, *wdl;
    cudaGetSymbolAddress((void**)&xT,  g_xT);
    cudaGetSymbolAddress((void**)&wtT, g_WtT);
    cudaGetSymbolAddress((void**)&xh,  g_xh);
    cudaGetSymbolAddress((void**)&xl,  g_xl);
    cudaGetSymbolAddress((void**)&wch, g_Wch);
    cudaGetSymbolAddress((void**)&wcl, g_Wcl);
    cudaGetSymbolAddress((void**)&wgh, g_Wgh);
    cudaGetSymbolAddress((void**)&wgl, g_Wgl);
    cudaGetSymbolAddress((void**)&wdh, g_Wdh);
    cudaGetSymbolAddress((void**)&wdl, g_Wdl);

    static int attr_set = 0;
    if (!attr_set) {
        cudaFuncSetAttribute(dtn_cg_kernel, cudaFuncAttributeMaxDynamicSharedMemorySize, CG_SMEM);
        cudaFuncSetAttribute(dtn_out_kernel, cudaFuncAttributeMaxDynamicSharedMemorySize, OD_SMEM);
        attr_set = 1;
    }

    transpose_kernel<<<dim3(DM / 32, T_TOT / 32), dim3(32, 8)>>>(x, xT, T_TOT, DM);
    transpose_kernel<<<dim3(DM / 32, FFN / 32), dim3(32, 8)>>>(Wt, wtT, FFN, DM);
    split_bf16_kernel<<<(T_TOT * DM / 4 + 255) / 256, 256>>>((const float4*)x, xh, xl, T_TOT * DM / 4);
    transpose_split_bf16_kernel<<<dim3(FFN / 32, DM / 32), dim3(32, 8)>>>(Wc, wch, wcl, DM, FFN);
    transpose_split_bf16_kernel<<<dim3(FFN / 32, DM / 32), dim3(32, 8)>>>(Wg, wgh, wgl, DM, FFN);
    transpose_split_bf16_kernel<<<dim3(DM / 32, FFN / 32), dim3(32, 8)>>>(Wd, wdh, wdl, FFN, DM);

    dtn_trop_kernel<<<dim3(FFN / 64, T_TOT / 128), 256>>>(bt);
    dtn_cg_kernel<<<dim3(FFN / 64, T_TOT / 128), 256, CG_SMEM>>>(
        sl_cvx, of_cvx, sl_ccv, of_ccv, alpha, bc, bg);
    dtn_out_kernel<<<dim3(DM / 64, T_TOT / 128), 256, OD_SMEM>>>(bd, out);
}